// round 3
// baseline (speedup 1.0000x reference)
#include <cuda_runtime.h>
#include <math.h>
#include <stdint.h>

#define LQ 256
#define BQ 64
#define DQ 1024
#define VQ 32000
#define MQ (LQ * BQ)          // 16384 rows for projections

// ---------------- scratch (static device globals; no allocation) ----------------
__device__ float g_x [LQ * BQ * DQ];   // current layer input / bw output
__device__ float g_h [LQ * BQ * DQ];   // fw output ("first")
__device__ float g_xi[LQ * BQ * DQ];
__device__ float g_xf[LQ * BQ * DQ];
__device__ float g_xc[LQ * BQ * DQ];
__device__ float g_cbuf[2 * BQ * DQ];  // double-buffered recurrent state
__device__ unsigned g_bar_count;       // zero-initialized
__device__ unsigned g_bar_gen;

// ---------------- embedding gather ----------------
__global__ __launch_bounds__(256) void embed_kernel(
    const int* __restrict__ xs, const float* __restrict__ emb, float* __restrict__ x)
{
    int i = blockIdx.x * 256 + threadIdx.x;     // over MQ*DQ/4 float4's
    int tokpos = i >> 8;                        // DQ/4 = 256 float4 per row
    int d4 = i & 255;
    int tok = xs[tokpos];
    tok = min(max(tok, 0), VQ - 1);
    ((float4*)x)[i] = ((const float4*)(emb + (size_t)tok * DQ))[d4];
}

__global__ __launch_bounds__(256) void zero_kernel(float* __restrict__ p, int n)
{
    int i = blockIdx.x * 256 + threadIdx.x;
    if (i < n) p[i] = 0.0f;
}

// ---------------- fp32 SGEMM + bias:  C[M,N] = A[M,K] @ W[K,N] + bias ----------------
// M=16384, N=K=1024 fixed. BM=BN=128, BK=8, 256 threads, 8x8 per thread.
#define GBM 128
#define GBN 128
#define GBK 8

__global__ __launch_bounds__(256) void sgemm_bias(
    const float* __restrict__ A, const float* __restrict__ W,
    const float* __restrict__ bias, float* __restrict__ C)
{
    __shared__ __align__(16) float As[GBK][GBM];   // transposed A tile
    __shared__ __align__(16) float Bs[GBK][GBN];

    const int tid = threadIdx.x;
    const int bx = blockIdx.x;                 // N tile index (0..7)
    const int by = blockIdx.y;                 // M tile index (0..127)

    const int arow = tid >> 1;                 // 0..127
    const int acol = (tid & 1) << 2;           // 0 or 4
    const int brow = tid >> 5;                 // 0..7
    const int bcol = (tid & 31) << 2;          // 0..124
    const int tr = tid >> 4;                   // 0..15
    const int tc = tid & 15;                   // 0..15

    const float* Aptr = A + (size_t)(by * GBM + arow) * DQ + acol;
    const float* Wptr = W + (size_t)brow * DQ + bx * GBN + bcol;

    float acc[8][8] = {};

    for (int kt = 0; kt < DQ; kt += GBK) {
        float4 av = *(const float4*)(Aptr + kt);
        As[acol + 0][arow] = av.x;
        As[acol + 1][arow] = av.y;
        As[acol + 2][arow] = av.z;
        As[acol + 3][arow] = av.w;
        *(float4*)&Bs[brow][bcol] = *(const float4*)(Wptr + (size_t)kt * DQ);
        __syncthreads();

        #pragma unroll
        for (int k = 0; k < GBK; k++) {
            float rm[8], rn[8];
            *(float4*)&rm[0] = *(const float4*)&As[k][tr * 8];
            *(float4*)&rm[4] = *(const float4*)&As[k][tr * 8 + 4];
            *(float4*)&rn[0] = *(const float4*)&Bs[k][tc * 8];
            *(float4*)&rn[4] = *(const float4*)&Bs[k][tc * 8 + 4];
            #pragma unroll
            for (int i = 0; i < 8; i++)
                #pragma unroll
                for (int j = 0; j < 8; j++)
                    acc[i][j] += rm[i] * rn[j];
        }
        __syncthreads();
    }

    float bv[8];
    *(float4*)&bv[0] = *(const float4*)(bias + bx * GBN + tc * 8);
    *(float4*)&bv[4] = *(const float4*)(bias + bx * GBN + tc * 8 + 4);

    #pragma unroll
    for (int i = 0; i < 8; i++) {
        int row = by * GBM + tr * 8 + i;
        float4 o0 = make_float4(acc[i][0] + bv[0], acc[i][1] + bv[1],
                                acc[i][2] + bv[2], acc[i][3] + bv[3]);
        float4 o1 = make_float4(acc[i][4] + bv[4], acc[i][5] + bv[5],
                                acc[i][6] + bv[6], acc[i][7] + bv[7]);
        float* cp = C + (size_t)row * DQ + bx * GBN + tc * 8;
        *(float4*)cp = o0;
        *(float4*)(cp + 4) = o1;
    }
}

// ---------------- persistent scan kernel ----------------
// 128 CTAs x 256 threads, all co-resident. CTA owns 8 output columns (same n for
// Wic and Wfc), weight slices live in dynamic SMEM for the whole scan.
#define NB_SCAN 128
#define SCAN_SMEM_BYTES ((DQ * 16 + BQ * 16) * 4)   // 69632

__device__ __forceinline__ void grid_sync()
{
    __syncthreads();
    if (threadIdx.x == 0) {
        __threadfence();
        volatile unsigned* genp = &g_bar_gen;
        unsigned gen = *genp;
        unsigned arrived = atomicAdd(&g_bar_count, 1u);
        if (arrived == NB_SCAN - 1) {
            g_bar_count = 0;
            __threadfence();
            *genp = gen + 1;
        } else {
            while (*genp == gen) { __nanosleep(64); }
        }
    }
    __syncthreads();
}

__global__ __launch_bounds__(256) void scan_kernel(
    const float* __restrict__ x,  const float* __restrict__ xi,
    const float* __restrict__ xf, const float* __restrict__ xc,
    const float* __restrict__ Wic, const float* __restrict__ Wfc,
    float* __restrict__ cbuf,     // [2][BQ*DQ]
    float* __restrict__ h, int reverse)
{
    extern __shared__ __align__(16) float smem[];
    float* Ws = smem;               // [DQ][16]: cols 0..7 = Wic slice, 8..15 = Wfc slice
    float* uv = smem + DQ * 16;     // [BQ][16]: u at [b][0..7], v at [b][8..15]

    const int tid = threadIdx.x;
    const int n0 = blockIdx.x * 8;

    for (int idx = tid; idx < DQ * 8; idx += 256) {
        int k = idx >> 3, n = idx & 7;
        Ws[k * 16 + n]     = Wic[(size_t)k * DQ + n0 + n];
        Ws[k * 16 + 8 + n] = Wfc[(size_t)k * DQ + n0 + n];
    }
    __syncthreads();

    const int q = tid & 3;          // quadrant: 0,1 -> u cols; 2,3 -> v cols
    const int b = tid >> 2;         // 0..63
    const float4* wq = (const float4*)Ws + q;   // Ws[k][q*4] = float4 index k*4+q

    for (int step = 0; step < LQ; step++) {
        const int t = reverse ? (LQ - 1 - step) : step;
        const float* cprev = cbuf + (step & 1) * (BQ * DQ);
        float* cnext = cbuf + ((step + 1) & 1) * (BQ * DQ);

        float a0 = 0.f, a1 = 0.f, a2 = 0.f, a3 = 0.f;
        const float4* crow = (const float4*)(cprev + (size_t)b * DQ);
        #pragma unroll 4
        for (int k4 = 0; k4 < DQ / 4; k4++) {
            float4 cv = __ldcg(crow + k4);
            float4 w0 = wq[(4 * k4 + 0) * 4];
            float4 w1 = wq[(4 * k4 + 1) * 4];
            float4 w2 = wq[(4 * k4 + 2) * 4];
            float4 w3 = wq[(4 * k4 + 3) * 4];
            a0 += cv.x * w0.x; a1 += cv.x * w0.y; a2 += cv.x * w0.z; a3 += cv.x * w0.w;
            a0 += cv.y * w1.x; a1 += cv.y * w1.y; a2 += cv.y * w1.z; a3 += cv.y * w1.w;
            a0 += cv.z * w2.x; a1 += cv.z * w2.y; a2 += cv.z * w2.z; a3 += cv.z * w2.w;
            a0 += cv.w * w3.x; a1 += cv.w * w3.y; a2 += cv.w * w3.z; a3 += cv.w * w3.w;
        }
        uv[b * 16 + q * 4 + 0] = a0;
        uv[b * 16 + q * 4 + 1] = a1;
        uv[b * 16 + q * 4 + 2] = a2;
        uv[b * 16 + q * 4 + 3] = a3;
        __syncthreads();

        // elementwise update: 64 b x 8 n = 512 outputs, 2 per thread
        #pragma unroll
        for (int rep = 0; rep < 2; rep++) {
            int rr = tid + rep * 256;
            int bb = rr >> 3, nn = rr & 7;
            int gn = n0 + nn;
            size_t off = ((size_t)t * BQ + bb) * DQ + gn;
            float uu = uv[bb * 16 + nn];
            float vv = uv[bb * 16 + 8 + nn];
            float iv = 1.0f / (1.0f + expf(-(xi[off] + uu)));
            float fv = 1.0f / (1.0f + expf(-(xf[off] + vv)));
            float cold = __ldcg(cprev + (size_t)bb * DQ + gn);
            float cn = iv * xc[off] + fv * cold;
            cnext[(size_t)bb * DQ + gn] = cn;
            h[off] = tanhf(cn) + x[off];
        }
        grid_sync();
    }
}

// ---------------- launcher ----------------
extern "C" void kernel_launch(void* const* d_in, const int* in_sizes, int n_in,
                              void* d_out, int out_size)
{
    (void)in_sizes; (void)n_in; (void)out_size;

    cudaFuncSetAttribute(scan_kernel, cudaFuncAttributeMaxDynamicSharedMemorySize,
                         SCAN_SMEM_BYTES);

    const int*   xs  = (const int*)d_in[0];
    const float* emb = (const float*)d_in[1];
    const float* P[16];
    for (int i = 0; i < 16; i++) P[i] = (const float*)d_in[2 + i];
    // P: 0=fw_Wix 1=fw_Wic 2=fw_Wfx 3=fw_Wfc 4=fw_Wcx 5=fw_bi 6=fw_bf 7=fw_bc
    //    8=bw_Wix 9=bw_Wic 10=bw_Wfx 11=bw_Wfc 12=bw_Wcx 13=bw_bi 14=bw_bf 15=bw_bc

    float *px, *ph, *pxi, *pxf, *pxc, *pcb;
    cudaGetSymbolAddress((void**)&px,  g_x);
    cudaGetSymbolAddress((void**)&ph,  g_h);
    cudaGetSymbolAddress((void**)&pxi, g_xi);
    cudaGetSymbolAddress((void**)&pxf, g_xf);
    cudaGetSymbolAddress((void**)&pxc, g_xc);
    cudaGetSymbolAddress((void**)&pcb, g_cbuf);
    float* out = (float*)d_out;

    embed_kernel<<<MQ * DQ / 4 / 256, 256>>>(xs, emb, px);
    zero_kernel<<<(2 * BQ * DQ + 255) / 256, 256>>>(pcb, 2 * BQ * DQ);

    dim3 ggrid(DQ / GBN, MQ / GBM);   // (8, 128)
    for (int layer = 0; layer < 2; layer++) {
        // forward direction
        sgemm_bias<<<ggrid, 256>>>(px, P[0], P[5], pxi);
        sgemm_bias<<<ggrid, 256>>>(px, P[2], P[6], pxf);
        sgemm_bias<<<ggrid, 256>>>(px, P[4], P[7], pxc);
        scan_kernel<<<NB_SCAN, 256, SCAN_SMEM_BYTES>>>(px, pxi, pxf, pxc,
                                                       P[1], P[3], pcb, ph, 0);
        // backward direction
        sgemm_bias<<<ggrid, 256>>>(ph, P[8],  P[13], pxi);
        sgemm_bias<<<ggrid, 256>>>(ph, P[10], P[14], pxf);
        sgemm_bias<<<ggrid, 256>>>(ph, P[12], P[15], pxc);
        float* ho = (layer == 1) ? out : px;
        scan_kernel<<<NB_SCAN, 256, SCAN_SMEM_BYTES>>>(ph, pxi, pxf, pxc,
                                                       P[9], P[11], pcb, ho, 1);
    }
}

// round 4
// speedup vs baseline: 1.9360x; 1.9360x over previous
#include <cuda_runtime.h>
#include <math.h>
#include <stdint.h>

#define LQ 256
#define BQ 64
#define DQ 1024
#define VQ 32000
#define MQ (LQ * BQ)          // 16384 rows for projections

// ---------------- scratch (static device globals; no allocation) ----------------
__device__ float g_x [LQ * BQ * DQ];   // current layer input / bw output
__device__ float g_h [LQ * BQ * DQ];   // fw output ("first")
__device__ float g_xi[LQ * BQ * DQ];
__device__ float g_xf[LQ * BQ * DQ];
__device__ float g_xc[LQ * BQ * DQ];
__device__ float g_cbuf[2 * BQ * DQ];  // double-buffered recurrent state
__device__ unsigned g_bar_count;       // zero-initialized
__device__ unsigned g_bar_gen;

// ---------------- embedding gather ----------------
__global__ __launch_bounds__(256) void embed_kernel(
    const int* __restrict__ xs, const float* __restrict__ emb, float* __restrict__ x)
{
    int i = blockIdx.x * 256 + threadIdx.x;     // over MQ*DQ/4 float4's
    int tokpos = i >> 8;                        // DQ/4 = 256 float4 per row
    int d4 = i & 255;
    int tok = xs[tokpos];
    tok = min(max(tok, 0), VQ - 1);
    ((float4*)x)[i] = ((const float4*)(emb + (size_t)tok * DQ))[d4];
}

__global__ __launch_bounds__(256) void zero_kernel(float* __restrict__ p, int n)
{
    int i = blockIdx.x * 256 + threadIdx.x;
    if (i < n) p[i] = 0.0f;
}

// ---------------- fp32 SGEMM + bias:  C[M,N] = A[M,K] @ W[K,N] + bias ----------------
#define GBM 128
#define GBN 128
#define GBK 8

__global__ __launch_bounds__(256) void sgemm_bias(
    const float* __restrict__ A, const float* __restrict__ W,
    const float* __restrict__ bias, float* __restrict__ C)
{
    __shared__ __align__(16) float As[GBK][GBM];   // transposed A tile
    __shared__ __align__(16) float Bs[GBK][GBN];

    const int tid = threadIdx.x;
    const int bx = blockIdx.x;                 // N tile index (0..7)
    const int by = blockIdx.y;                 // M tile index (0..127)

    const int arow = tid >> 1;                 // 0..127
    const int acol = (tid & 1) << 2;           // 0 or 4
    const int brow = tid >> 5;                 // 0..7
    const int bcol = (tid & 31) << 2;          // 0..124
    const int tr = tid >> 4;                   // 0..15
    const int tc = tid & 15;                   // 0..15

    const float* Aptr = A + (size_t)(by * GBM + arow) * DQ + acol;
    const float* Wptr = W + (size_t)brow * DQ + bx * GBN + bcol;

    float acc[8][8] = {};

    for (int kt = 0; kt < DQ; kt += GBK) {
        float4 av = *(const float4*)(Aptr + kt);
        As[acol + 0][arow] = av.x;
        As[acol + 1][arow] = av.y;
        As[acol + 2][arow] = av.z;
        As[acol + 3][arow] = av.w;
        *(float4*)&Bs[brow][bcol] = *(const float4*)(Wptr + (size_t)kt * DQ);
        __syncthreads();

        #pragma unroll
        for (int k = 0; k < GBK; k++) {
            float rm[8], rn[8];
            *(float4*)&rm[0] = *(const float4*)&As[k][tr * 8];
            *(float4*)&rm[4] = *(const float4*)&As[k][tr * 8 + 4];
            *(float4*)&rn[0] = *(const float4*)&Bs[k][tc * 8];
            *(float4*)&rn[4] = *(const float4*)&Bs[k][tc * 8 + 4];
            #pragma unroll
            for (int i = 0; i < 8; i++)
                #pragma unroll
                for (int j = 0; j < 8; j++)
                    acc[i][j] += rm[i] * rn[j];
        }
        __syncthreads();
    }

    float bv[8];
    *(float4*)&bv[0] = *(const float4*)(bias + bx * GBN + tc * 8);
    *(float4*)&bv[4] = *(const float4*)(bias + bx * GBN + tc * 8 + 4);

    #pragma unroll
    for (int i = 0; i < 8; i++) {
        int row = by * GBM + tr * 8 + i;
        float4 o0 = make_float4(acc[i][0] + bv[0], acc[i][1] + bv[1],
                                acc[i][2] + bv[2], acc[i][3] + bv[3]);
        float4 o1 = make_float4(acc[i][4] + bv[4], acc[i][5] + bv[5],
                                acc[i][6] + bv[6], acc[i][7] + bv[7]);
        float* cp = C + (size_t)row * DQ + bx * GBN + tc * 8;
        *(float4*)cp = o0;
        *(float4*)(cp + 4) = o1;
    }
}

// ---------------- persistent scan kernel (tf32 mma) ----------------
// 128 CTAs x 256 threads (8 warps). CTA owns 8 output columns for both Wic (u)
// and Wfc (v) => per-step GEMM U[64,16] = C[64,1024] @ Ws[1024,16] via
// mma.sync.m16n8k8 tf32. Warp w owns K-slice [w*128, w*128+128); split-K
// partials reduced through SMEM. Weights pre-laid in SMEM in fragment order
// (tf32-converted) ONCE per scan. A (state c) loaded fragment-direct from L2
// with __ldcg float2 using the k-permutation g(f) = (f%4)*2 + f/4 applied to
// both A and B (sum over k is permutation-invariant).
#define NB_SCAN 128
// SMEM: Bfrag 128 ksteps * 2 nfrags * 32 lanes * 8B = 64 KB, partials 8*64*16*4 = 32 KB
#define SCAN_SMEM_BYTES (65536 + 32768)

__device__ __forceinline__ void grid_sync()
{
    __syncthreads();
    if (threadIdx.x == 0) {
        __threadfence();
        volatile unsigned* genp = &g_bar_gen;
        unsigned gen = *genp;
        unsigned arrived = atomicAdd(&g_bar_count, 1u);
        if (arrived == NB_SCAN - 1) {
            g_bar_count = 0;
            __threadfence();
            *genp = gen + 1;
        } else {
            while (*genp == gen) { __nanosleep(64); }
        }
    }
    __syncthreads();
}

__device__ __forceinline__ uint32_t f32_to_tf32(float f)
{
    uint32_t u;
    asm("cvt.rna.tf32.f32 %0, %1;" : "=r"(u) : "f"(f));
    return u;
}

__device__ __forceinline__ void mma_tf32(float d[4],
    uint32_t a0, uint32_t a1, uint32_t a2, uint32_t a3,
    uint32_t b0, uint32_t b1)
{
    asm volatile(
        "mma.sync.aligned.m16n8k8.row.col.f32.tf32.tf32.f32 "
        "{%0,%1,%2,%3}, {%4,%5,%6,%7}, {%8,%9}, {%0,%1,%2,%3};"
        : "+f"(d[0]), "+f"(d[1]), "+f"(d[2]), "+f"(d[3])
        : "r"(a0), "r"(a1), "r"(a2), "r"(a3), "r"(b0), "r"(b1));
}

__global__ __launch_bounds__(256) void scan_kernel(
    const float* __restrict__ x,  const float* __restrict__ xi,
    const float* __restrict__ xf, const float* __restrict__ xc,
    const float* __restrict__ Wic, const float* __restrict__ Wfc,
    float* __restrict__ cbuf,     // [2][BQ*DQ]
    float* __restrict__ h, int reverse)
{
    extern __shared__ __align__(16) char smem_raw[];
    uint2* Bs   = (uint2*)smem_raw;                  // [128 ksteps][2 nf][32 lanes]
    float* part = (float*)(smem_raw + 65536);        // [8 warps][64 b][16 cols]

    const int tid  = threadIdx.x;
    const int lane = tid & 31;
    const int w    = tid >> 5;
    const int gid  = lane >> 2;       // groupID 0..7
    const int tig  = lane & 3;        // threadID in group
    const int n0   = blockIdx.x * 8;  // this CTA's output column base

    // ---- pre-lay weights in fragment order, tf32-converted (once per scan) ----
    // B frag (m16n8k8, col-major): lane holds rows {tig, tig+4} of col gid.
    // With permutation g: global k = k0 + 2*tig (+0/+1), consecutive -> float2.
    for (int idx = tid; idx < 128 * 2 * 32; idx += 256) {
        int l  = idx & 31;
        int nf = (idx >> 5) & 1;
        int ks = idx >> 6;
        int kg = ks * 8 + 2 * (l & 3);
        int col = n0 + (l >> 2);
        const float* M = nf ? Wfc : Wic;
        uint2 v;
        v.x = f32_to_tf32(M[(size_t)kg * DQ + col]);
        v.y = f32_to_tf32(M[(size_t)(kg + 1) * DQ + col]);
        Bs[idx] = v;
    }
    __syncthreads();

    const int ks0 = w * 16;   // warp's k-step range

    for (int step = 0; step < LQ; step++) {
        const int t = reverse ? (LQ - 1 - step) : step;
        const float* cprev = cbuf + (step & 1) * (BQ * DQ);
        float* cnext = cbuf + ((step + 1) & 1) * (BQ * DQ);

        float acc[4][2][4];
        #pragma unroll
        for (int m = 0; m < 4; m++)
            #pragma unroll
            for (int nf = 0; nf < 2; nf++)
                #pragma unroll
                for (int r = 0; r < 4; r++) acc[m][nf][r] = 0.f;

        #pragma unroll 4
        for (int ks = 0; ks < 16; ks++) {
            int kstep = ks0 + ks;
            uint2 bu = Bs[(kstep * 2 + 0) * 32 + lane];
            uint2 bv = Bs[(kstep * 2 + 1) * 32 + lane];
            int kg = kstep * 8 + 2 * tig;
            const float* abase = cprev + (size_t)gid * DQ + kg;
            #pragma unroll
            for (int m = 0; m < 4; m++) {
                float2 alo = __ldcg((const float2*)(abase + (size_t)(m * 16) * DQ));
                float2 ahi = __ldcg((const float2*)(abase + (size_t)(m * 16 + 8) * DQ));
                uint32_t a0 = f32_to_tf32(alo.x);
                uint32_t a2 = f32_to_tf32(alo.y);
                uint32_t a1 = f32_to_tf32(ahi.x);
                uint32_t a3 = f32_to_tf32(ahi.y);
                mma_tf32(acc[m][0], a0, a1, a2, a3, bu.x, bu.y);
                mma_tf32(acc[m][1], a0, a1, a2, a3, bv.x, bv.y);
            }
        }

        // ---- write split-K partials: part[w][b][col] ----
        #pragma unroll
        for (int m = 0; m < 4; m++) {
            #pragma unroll
            for (int nf = 0; nf < 2; nf++) {
                int col = nf * 8 + 2 * tig;
                int b0r = m * 16 + gid;
                float2* p0 = (float2*)&part[((w * 64) + b0r) * 16 + col];
                float2* p1 = (float2*)&part[((w * 64) + b0r + 8) * 16 + col];
                *p0 = make_float2(acc[m][nf][0], acc[m][nf][1]);
                *p1 = make_float2(acc[m][nf][2], acc[m][nf][3]);
            }
        }
        __syncthreads();

        // ---- reduce over warps + elementwise update: 64b x 8n, 2 per thread ----
        #pragma unroll
        for (int rep = 0; rep < 2; rep++) {
            int rr = tid + rep * 256;
            int bb = rr >> 3, nn = rr & 7;
            int gn = n0 + nn;
            float uu = 0.f, vv = 0.f;
            #pragma unroll
            for (int ww = 0; ww < 8; ww++) {
                uu += part[((ww * 64) + bb) * 16 + nn];
                vv += part[((ww * 64) + bb) * 16 + 8 + nn];
            }
            size_t off = ((size_t)t * BQ + bb) * DQ + gn;
            float iv = 1.0f / (1.0f + expf(-(xi[off] + uu)));
            float fv = 1.0f / (1.0f + expf(-(xf[off] + vv)));
            float cold = __ldcg(cprev + (size_t)bb * DQ + gn);
            float cn = iv * xc[off] + fv * cold;
            cnext[(size_t)bb * DQ + gn] = cn;
            h[off] = tanhf(cn) + x[off];
        }
        grid_sync();
    }
}

// ---------------- launcher ----------------
extern "C" void kernel_launch(void* const* d_in, const int* in_sizes, int n_in,
                              void* d_out, int out_size)
{
    (void)in_sizes; (void)n_in; (void)out_size;

    cudaFuncSetAttribute(scan_kernel, cudaFuncAttributeMaxDynamicSharedMemorySize,
                         SCAN_SMEM_BYTES);

    const int*   xs  = (const int*)d_in[0];
    const float* emb = (const float*)d_in[1];
    const float* P[16];
    for (int i = 0; i < 16; i++) P[i] = (const float*)d_in[2 + i];
    // P: 0=fw_Wix 1=fw_Wic 2=fw_Wfx 3=fw_Wfc 4=fw_Wcx 5=fw_bi 6=fw_bf 7=fw_bc
    //    8=bw_Wix 9=bw_Wic 10=bw_Wfx 11=bw_Wfc 12=bw_Wcx 13=bw_bi 14=bw_bf 15=bw_bc

    float *px, *ph, *pxi, *pxf, *pxc, *pcb;
    cudaGetSymbolAddress((void**)&px,  g_x);
    cudaGetSymbolAddress((void**)&ph,  g_h);
    cudaGetSymbolAddress((void**)&pxi, g_xi);
    cudaGetSymbolAddress((void**)&pxf, g_xf);
    cudaGetSymbolAddress((void**)&pxc, g_xc);
    cudaGetSymbolAddress((void**)&pcb, g_cbuf);
    float* out = (float*)d_out;

    embed_kernel<<<MQ * DQ / 4 / 256, 256>>>(xs, emb, px);
    zero_kernel<<<(2 * BQ * DQ + 255) / 256, 256>>>(pcb, 2 * BQ * DQ);

    dim3 ggrid(DQ / GBN, MQ / GBM);   // (8, 128)
    for (int layer = 0; layer < 2; layer++) {
        // forward direction
        sgemm_bias<<<ggrid, 256>>>(px, P[0], P[5], pxi);
        sgemm_bias<<<ggrid, 256>>>(px, P[2], P[6], pxf);
        sgemm_bias<<<ggrid, 256>>>(px, P[4], P[7], pxc);
        scan_kernel<<<NB_SCAN, 256, SCAN_SMEM_BYTES>>>(px, pxi, pxf, pxc,
                                                       P[1], P[3], pcb, ph, 0);
        // backward direction
        sgemm_bias<<<ggrid, 256>>>(ph, P[8],  P[13], pxi);
        sgemm_bias<<<ggrid, 256>>>(ph, P[10], P[14], pxf);
        sgemm_bias<<<ggrid, 256>>>(ph, P[12], P[15], pxc);
        float* ho = (layer == 1) ? out : px;
        scan_kernel<<<NB_SCAN, 256, SCAN_SMEM_BYTES>>>(ph, pxi, pxf, pxc,
                                                       P[9], P[11], pcb, ho, 1);
    }
}

// round 6
// speedup vs baseline: 2.2767x; 1.1760x over previous
#include <cuda_runtime.h>
#include <math.h>
#include <stdint.h>

#define LQ 256
#define BQ 64
#define DQ 1024
#define VQ 32000
#define MQ (LQ * BQ)          // 16384 rows for projections

// ---------------- scratch (static device globals; no allocation) ----------------
__device__ float g_x [LQ * BQ * DQ];   // current layer input / bw output
__device__ float g_h [LQ * BQ * DQ];   // fw output ("first")
__device__ float g_xi[LQ * BQ * DQ];
__device__ float g_xf[LQ * BQ * DQ];
__device__ float g_xc[LQ * BQ * DQ];
__device__ float g_cbuf[2 * BQ * DQ];  // double-buffered recurrent state
__device__ unsigned g_bar_count;       // zero-initialized
__device__ unsigned g_bar_gen;

// ---------------- embedding gather ----------------
__global__ __launch_bounds__(256) void embed_kernel(
    const int* __restrict__ xs, const float* __restrict__ emb, float* __restrict__ x)
{
    int i = blockIdx.x * 256 + threadIdx.x;     // over MQ*DQ/4 float4's
    int tokpos = i >> 8;                        // DQ/4 = 256 float4 per row
    int d4 = i & 255;
    int tok = xs[tokpos];
    tok = min(max(tok, 0), VQ - 1);
    ((float4*)x)[i] = ((const float4*)(emb + (size_t)tok * DQ))[d4];
}

__global__ __launch_bounds__(256) void zero_kernel(float* __restrict__ p, int n)
{
    int i = blockIdx.x * 256 + threadIdx.x;
    if (i < n) p[i] = 0.0f;
}

// ---------------- tf32 mma helpers ----------------
__device__ __forceinline__ uint32_t f32_to_tf32(float f)
{
    uint32_t u;
    asm("cvt.rna.tf32.f32 %0, %1;" : "=r"(u) : "f"(f));
    return u;
}

// 3xTF32 split: v = hi + lo, both RNA-rounded tf32 values (fp32 container).
__device__ __forceinline__ void split_tf32(float v, uint32_t& hi, uint32_t& lo)
{
    uint32_t h;
    asm("cvt.rna.tf32.f32 %0, %1;" : "=r"(h) : "f"(v));
    float r = v - __uint_as_float(h);
    uint32_t l;
    asm("cvt.rna.tf32.f32 %0, %1;" : "=r"(l) : "f"(r));
    hi = h; lo = l;
}

__device__ __forceinline__ void mma_tf32(float d[4],
    uint32_t a0, uint32_t a1, uint32_t a2, uint32_t a3,
    uint32_t b0, uint32_t b1)
{
    asm volatile(
        "mma.sync.aligned.m16n8k8.row.col.f32.tf32.tf32.f32 "
        "{%0,%1,%2,%3}, {%4,%5,%6,%7}, {%8,%9}, {%0,%1,%2,%3};"
        : "+f"(d[0]), "+f"(d[1]), "+f"(d[2]), "+f"(d[3])
        : "r"(a0), "r"(a1), "r"(a2), "r"(a3), "r"(b0), "r"(b1));
}

// ---------------- 3xTF32 tensor-core GEMM + bias: C = A@W + bias --------------
// M=16384, N=K=1024. BM=128, BN=128, BK=16, 256 threads (8 warps, 2x4 warp grid,
// warp tile 64x32). cp.async double-buffered smem. 3xTF32 error compensation:
// acc += hiA*hiB + loA*hiB + hiA*loB  (fp32-grade accuracy on tensor cores).
#define TBM 128
#define TBN 128
#define TBK 16
#define APAD 4
#define BPAD 4

__global__ __launch_bounds__(256) void sgemm_tf32x3(
    const float* __restrict__ A, const float* __restrict__ W,
    const float* __restrict__ bias, float* __restrict__ C)
{
    __shared__ __align__(16) float As[2][TBM][TBK + APAD];
    __shared__ __align__(16) float Bs[2][TBK][TBN + BPAD];

    const int tid  = threadIdx.x;
    const int lane = tid & 31;
    const int w    = tid >> 5;
    const int gid  = lane >> 2;
    const int tig  = lane & 3;
    const int wm0  = (w >> 2) * 64;   // warp m offset in tile
    const int wn0  = (w & 3) * 32;    // warp n offset in tile
    const int m0   = blockIdx.y * TBM;
    const int n0   = blockIdx.x * TBN;

    float acc[4][4][4];
    #pragma unroll
    for (int mf = 0; mf < 4; mf++)
        #pragma unroll
        for (int nf = 0; nf < 4; nf++)
            #pragma unroll
            for (int r = 0; r < 4; r++) acc[mf][nf][r] = 0.f;

    auto load_tiles = [&](int it, int buf) {
        int k0 = it * TBK;
        #pragma unroll
        for (int j = 0; j < 2; j++) {
            int c = tid + 256 * j;
            int row = c >> 2, seg = c & 3;
            const float* src = A + (size_t)(m0 + row) * DQ + k0 + seg * 4;
            uint32_t dst = (uint32_t)__cvta_generic_to_shared(&As[buf][row][seg * 4]);
            asm volatile("cp.async.ca.shared.global [%0], [%1], 16;" :: "r"(dst), "l"(src));
        }
        #pragma unroll
        for (int j = 0; j < 2; j++) {
            int c = tid + 256 * j;
            int k = c >> 5, seg = c & 31;
            const float* src = W + (size_t)(k0 + k) * DQ + n0 + seg * 4;
            uint32_t dst = (uint32_t)__cvta_generic_to_shared(&Bs[buf][k][seg * 4]);
            asm volatile("cp.async.ca.shared.global [%0], [%1], 16;" :: "r"(dst), "l"(src));
        }
        asm volatile("cp.async.commit_group;");
    };

    load_tiles(0, 0);

    const int NIT = DQ / TBK;   // 64
    for (int it = 0; it < NIT; it++) {
        int buf = it & 1;
        if (it + 1 < NIT) {
            load_tiles(it + 1, buf ^ 1);
            asm volatile("cp.async.wait_group 1;");
        } else {
            asm volatile("cp.async.wait_group 0;");
        }
        __syncthreads();

        #pragma unroll
        for (int ks = 0; ks < 2; ks++) {
            int kk = ks * 8;
            uint32_t ah[4][4], al[4][4];
            #pragma unroll
            for (int mf = 0; mf < 4; mf++) {
                int r = wm0 + mf * 16;
                split_tf32(As[buf][r + gid][kk + tig],         ah[mf][0], al[mf][0]);
                split_tf32(As[buf][r + gid + 8][kk + tig],     ah[mf][1], al[mf][1]);
                split_tf32(As[buf][r + gid][kk + tig + 4],     ah[mf][2], al[mf][2]);
                split_tf32(As[buf][r + gid + 8][kk + tig + 4], ah[mf][3], al[mf][3]);
            }
            uint32_t bh[4][2], bl[4][2];
            #pragma unroll
            for (int nf = 0; nf < 4; nf++) {
                int cN = wn0 + nf * 8 + gid;
                split_tf32(Bs[buf][kk + tig][cN],     bh[nf][0], bl[nf][0]);
                split_tf32(Bs[buf][kk + tig + 4][cN], bh[nf][1], bl[nf][1]);
            }
            #pragma unroll
            for (int mf = 0; mf < 4; mf++)
                #pragma unroll
                for (int nf = 0; nf < 4; nf++) {
                    mma_tf32(acc[mf][nf], ah[mf][0], ah[mf][1], ah[mf][2], ah[mf][3],
                             bh[nf][0], bh[nf][1]);
                    mma_tf32(acc[mf][nf], al[mf][0], al[mf][1], al[mf][2], al[mf][3],
                             bh[nf][0], bh[nf][1]);
                    mma_tf32(acc[mf][nf], ah[mf][0], ah[mf][1], ah[mf][2], ah[mf][3],
                             bl[nf][0], bl[nf][1]);
                }
        }
        __syncthreads();
    }

    // epilogue: bias + store (c0,c1 adjacent cols -> float2)
    #pragma unroll
    for (int mf = 0; mf < 4; mf++) {
        #pragma unroll
        for (int nf = 0; nf < 4; nf++) {
            int r0 = m0 + wm0 + mf * 16 + gid;
            int cN = n0 + wn0 + nf * 8 + 2 * tig;
            float2 bv = *(const float2*)(bias + cN);
            float2 o0 = make_float2(acc[mf][nf][0] + bv.x, acc[mf][nf][1] + bv.y);
            float2 o1 = make_float2(acc[mf][nf][2] + bv.x, acc[mf][nf][3] + bv.y);
            *(float2*)(C + (size_t)r0 * DQ + cN) = o0;
            *(float2*)(C + (size_t)(r0 + 8) * DQ + cN) = o1;
        }
    }
}

// ---------------- persistent scan kernel (tf32 mma) ----------------
#define NB_SCAN 128
// SMEM: Bfrag 128 ksteps * 2 nfrags * 32 lanes * 8B = 64 KB, partials 8*64*16*4 = 32 KB
#define SCAN_SMEM_BYTES (65536 + 32768)

__device__ __forceinline__ void grid_sync()
{
    __syncthreads();
    if (threadIdx.x == 0) {
        __threadfence();
        volatile unsigned* genp = &g_bar_gen;
        unsigned gen = *genp;
        unsigned arrived = atomicAdd(&g_bar_count, 1u);
        if (arrived == NB_SCAN - 1) {
            g_bar_count = 0;
            __threadfence();
            *genp = gen + 1;
        } else {
            while (*genp == gen) { }
        }
    }
    __syncthreads();
}

__global__ __launch_bounds__(256) void scan_kernel(
    const float* __restrict__ x,  const float* __restrict__ xi,
    const float* __restrict__ xf, const float* __restrict__ xc,
    const float* __restrict__ Wic, const float* __restrict__ Wfc,
    float* __restrict__ cbuf,     // [2][BQ*DQ]
    float* __restrict__ h, int reverse)
{
    extern __shared__ __align__(16) char smem_raw[];
    uint2* Bs   = (uint2*)smem_raw;                  // [128 ksteps][2 nf][32 lanes]
    float* part = (float*)(smem_raw + 65536);        // [8 warps][64 b][16 cols]

    const int tid  = threadIdx.x;
    const int lane = tid & 31;
    const int w    = tid >> 5;
    const int gid  = lane >> 2;       // groupID 0..7
    const int tig  = lane & 3;        // threadID in group
    const int n0   = blockIdx.x * 8;  // this CTA's output column base

    // ---- pre-lay weights in fragment order, tf32-converted (once per scan) ----
    for (int idx = tid; idx < 128 * 2 * 32; idx += 256) {
        int l  = idx & 31;
        int nf = (idx >> 5) & 1;
        int ks = idx >> 6;
        int kg = ks * 8 + 2 * (l & 3);
        int col = n0 + (l >> 2);
        const float* M = nf ? Wfc : Wic;
        uint2 v;
        v.x = f32_to_tf32(M[(size_t)kg * DQ + col]);
        v.y = f32_to_tf32(M[(size_t)(kg + 1) * DQ + col]);
        Bs[idx] = v;
    }
    __syncthreads();

    const int ks0 = w * 16;   // warp's k-step range

    for (int step = 0; step < LQ; step++) {
        const int t = reverse ? (LQ - 1 - step) : step;
        const float* cprev = cbuf + (step & 1) * (BQ * DQ);
        float* cnext = cbuf + ((step + 1) & 1) * (BQ * DQ);

        float acc[4][2][4];
        #pragma unroll
        for (int m = 0; m < 4; m++)
            #pragma unroll
            for (int nf = 0; nf < 2; nf++)
                #pragma unroll
                for (int r = 0; r < 4; r++) acc[m][nf][r] = 0.f;

        #pragma unroll 4
        for (int ks = 0; ks < 16; ks++) {
            int kstep = ks0 + ks;
            uint2 bu = Bs[(kstep * 2 + 0) * 32 + lane];
            uint2 bv = Bs[(kstep * 2 + 1) * 32 + lane];
            int kg = kstep * 8 + 2 * tig;
            const float* abase = cprev + (size_t)gid * DQ + kg;
            #pragma unroll
            for (int m = 0; m < 4; m++) {
                float2 alo = __ldcg((const float2*)(abase + (size_t)(m * 16) * DQ));
                float2 ahi = __ldcg((const float2*)(abase + (size_t)(m * 16 + 8) * DQ));
                uint32_t a0 = f32_to_tf32(alo.x);
                uint32_t a2 = f32_to_tf32(alo.y);
                uint32_t a1 = f32_to_tf32(ahi.x);
                uint32_t a3 = f32_to_tf32(ahi.y);
                mma_tf32(acc[m][0], a0, a1, a2, a3, bu.x, bu.y);
                mma_tf32(acc[m][1], a0, a1, a2, a3, bv.x, bv.y);
            }
        }

        // ---- write split-K partials: part[w][b][col] ----
        #pragma unroll
        for (int m = 0; m < 4; m++) {
            #pragma unroll
            for (int nf = 0; nf < 2; nf++) {
                int col = nf * 8 + 2 * tig;
                int b0r = m * 16 + gid;
                float2* p0 = (float2*)&part[((w * 64) + b0r) * 16 + col];
                float2* p1 = (float2*)&part[((w * 64) + b0r + 8) * 16 + col];
                *p0 = make_float2(acc[m][nf][0], acc[m][nf][1]);
                *p1 = make_float2(acc[m][nf][2], acc[m][nf][3]);
            }
        }
        __syncthreads();

        // ---- reduce over warps + elementwise update: 64b x 8n, 2 per thread ----
        #pragma unroll
        for (int rep = 0; rep < 2; rep++) {
            int rr = tid + rep * 256;
            int bb = rr >> 3, nn = rr & 7;
            int gn = n0 + nn;
            float uu = 0.f, vv = 0.f;
            #pragma unroll
            for (int ww = 0; ww < 8; ww++) {
                uu += part[((ww * 64) + bb) * 16 + nn];
                vv += part[((ww * 64) + bb) * 16 + 8 + nn];
            }
            size_t off = ((size_t)t * BQ + bb) * DQ + gn;
            float iv = 1.0f / (1.0f + expf(-(xi[off] + uu)));
            float fv = 1.0f / (1.0f + expf(-(xf[off] + vv)));
            float cold = __ldcg(cprev + (size_t)bb * DQ + gn);
            float cn = iv * xc[off] + fv * cold;
            cnext[(size_t)bb * DQ + gn] = cn;
            h[off] = tanhf(cn) + x[off];
        }
        grid_sync();
    }
}

// ---------------- launcher ----------------
extern "C" void kernel_launch(void* const* d_in, const int* in_sizes, int n_in,
                              void* d_out, int out_size)
{
    (void)in_sizes; (void)n_in; (void)out_size;

    cudaFuncSetAttribute(scan_kernel, cudaFuncAttributeMaxDynamicSharedMemorySize,
                         SCAN_SMEM_BYTES);

    const int*   xs  = (const int*)d_in[0];
    const float* emb = (const float*)d_in[1];
    const float* P[16];
    for (int i = 0; i < 16; i++) P[i] = (const float*)d_in[2 + i];
    // P: 0=fw_Wix 1=fw_Wic 2=fw_Wfx 3=fw_Wfc 4=fw_Wcx 5=fw_bi 6=fw_bf 7=fw_bc
    //    8=bw_Wix 9=bw_Wic 10=bw_Wfx 11=bw_Wfc 12=bw_Wcx 13=bw_bi 14=bw_bf 15=bw_bc

    float *px, *ph, *pxi, *pxf, *pxc, *pcb;
    cudaGetSymbolAddress((void**)&px,  g_x);
    cudaGetSymbolAddress((void**)&ph,  g_h);
    cudaGetSymbolAddress((void**)&pxi, g_xi);
    cudaGetSymbolAddress((void**)&pxf, g_xf);
    cudaGetSymbolAddress((void**)&pxc, g_xc);
    cudaGetSymbolAddress((void**)&pcb, g_cbuf);
    float* out = (float*)d_out;

    embed_kernel<<<MQ * DQ / 4 / 256, 256>>>(xs, emb, px);
    zero_kernel<<<(2 * BQ * DQ + 255) / 256, 256>>>(pcb, 2 * BQ * DQ);

    dim3 ggrid(DQ / TBN, MQ / TBM);   // (8, 128)
    for (int layer = 0; layer < 2; layer++) {
        // forward direction
        sgemm_tf32x3<<<ggrid, 256>>>(px, P[0], P[5], pxi);
        sgemm_tf32x3<<<ggrid, 256>>>(px, P[2], P[6], pxf);
        sgemm_tf32x3<<<ggrid, 256>>>(px, P[4], P[7], pxc);
        scan_kernel<<<NB_SCAN, 256, SCAN_SMEM_BYTES>>>(px, pxi, pxf, pxc,
                                                       P[1], P[3], pcb, ph, 0);
        // backward direction
        sgemm_tf32x3<<<ggrid, 256>>>(ph, P[8],  P[13], pxi);
        sgemm_tf32x3<<<ggrid, 256>>>(ph, P[10], P[14], pxf);
        sgemm_tf32x3<<<ggrid, 256>>>(ph, P[12], P[15], pxc);
        float* ho = (layer == 1) ? out : px;
        scan_kernel<<<NB_SCAN, 256, SCAN_SMEM_BYTES>>>(ph, pxi, pxf, pxc,
                                                       P[9], P[11], pcb, ho, 1);
    }
}

// round 7
// speedup vs baseline: 2.4207x; 1.0633x over previous
#include <cuda_runtime.h>
#include <math.h>
#include <stdint.h>

#define LQ 256
#define BQ 64
#define DQ 1024
#define VQ 32000
#define MQ (LQ * BQ)          // 16384 rows for projections

// ---------------- scratch (static device globals; no allocation) ----------------
__device__ float g_x [LQ * BQ * DQ];   // current layer input / bw output
__device__ float g_h [LQ * BQ * DQ];   // fw output ("first")
__device__ float g_xi[LQ * BQ * DQ];
__device__ float g_xf[LQ * BQ * DQ];
__device__ float g_xc[LQ * BQ * DQ];
__device__ float g_cbuf[2 * BQ * DQ];  // double-buffered recurrent state
__device__ float g_ahi[LQ * BQ * DQ];  // pre-split GEMM A operand (hi)
__device__ float g_alo[LQ * BQ * DQ];  // pre-split GEMM A operand (lo)
__device__ float g_whi[6 * DQ * DQ];   // pre-split weights (hi): fwWix,fwWfx,fwWcx,bwWix,bwWfx,bwWcx
__device__ float g_wlo[6 * DQ * DQ];   // pre-split weights (lo)
__device__ unsigned g_bar_count;       // zero-initialized
__device__ unsigned g_bar_gen;

// ---------------- embedding gather ----------------
__global__ __launch_bounds__(256) void embed_kernel(
    const int* __restrict__ xs, const float* __restrict__ emb, float* __restrict__ x)
{
    int i = blockIdx.x * 256 + threadIdx.x;     // over MQ*DQ/4 float4's
    int tokpos = i >> 8;                        // DQ/4 = 256 float4 per row
    int d4 = i & 255;
    int tok = xs[tokpos];
    tok = min(max(tok, 0), VQ - 1);
    ((float4*)x)[i] = ((const float4*)(emb + (size_t)tok * DQ))[d4];
}

__global__ __launch_bounds__(256) void zero_kernel(float* __restrict__ p, int n)
{
    int i = blockIdx.x * 256 + threadIdx.x;
    if (i < n) p[i] = 0.0f;
}

// ---------------- tf32 helpers ----------------
__device__ __forceinline__ uint32_t f32_to_tf32(float f)
{
    uint32_t u;
    asm("cvt.rna.tf32.f32 %0, %1;" : "=r"(u) : "f"(f));
    return u;
}

__device__ __forceinline__ float tf32r(float f)
{
    uint32_t u;
    asm("cvt.rna.tf32.f32 %0, %1;" : "=r"(u) : "f"(f));
    return __uint_as_float(u);
}

__device__ __forceinline__ void mma_tf32(float d[4],
    uint32_t a0, uint32_t a1, uint32_t a2, uint32_t a3,
    uint32_t b0, uint32_t b1)
{
    asm volatile(
        "mma.sync.aligned.m16n8k8.row.col.f32.tf32.tf32.f32 "
        "{%0,%1,%2,%3}, {%4,%5,%6,%7}, {%8,%9}, {%0,%1,%2,%3};"
        : "+f"(d[0]), "+f"(d[1]), "+f"(d[2]), "+f"(d[3])
        : "r"(a0), "r"(a1), "r"(a2), "r"(a3), "r"(b0), "r"(b1));
}

// ---------------- hi/lo split kernel (RNA tf32 decomposition) ----------------
__global__ __launch_bounds__(256) void split_kernel(
    const float4* __restrict__ src, float4* __restrict__ hi, float4* __restrict__ lo, int n4)
{
    int i = blockIdx.x * 256 + threadIdx.x;
    if (i >= n4) return;
    float4 v = src[i];
    float4 h, l;
    h.x = tf32r(v.x); l.x = tf32r(v.x - h.x);
    h.y = tf32r(v.y); l.y = tf32r(v.y - h.y);
    h.z = tf32r(v.z); l.z = tf32r(v.z - h.z);
    h.w = tf32r(v.w); l.w = tf32r(v.w - h.w);
    hi[i] = h;
    lo[i] = l;
}

// ---------------- 3xTF32 pre-split GEMM + bias: C = A@W + bias ----------------
// Operands arrive pre-split into tf32-exact hi/lo fp32 buffers. Inner loop is
// pure LDS -> HMMA (no cvt/sub). acc += hiA*hiB + loA*hiB + hiA*loB.
#define TBM 128
#define TBN 128
#define TBK 16
#define APAD 4
#define BPAD 4
#define AS_STRIDE (TBK + APAD)          // 20
#define BS_STRIDE (TBN + BPAD)          // 132
#define AS_TILE (TBM * AS_STRIDE)       // 2560 floats per buf
#define BS_TILE (TBK * BS_STRIDE)       // 2112 floats per buf
// dynamic smem layout (floats): Ash[2], Asl[2], Bsh[2], Bsl[2]
#define OFF_ASH 0
#define OFF_ASL (2 * AS_TILE)
#define OFF_BSH (4 * AS_TILE)
#define OFF_BSL (4 * AS_TILE + 2 * BS_TILE)
#define GEMM_SMEM_BYTES ((4 * AS_TILE + 4 * BS_TILE) * 4)   // 74752

__global__ __launch_bounds__(256) void sgemm_presplit(
    const float* __restrict__ Ahi, const float* __restrict__ Alo,
    const float* __restrict__ Whi, const float* __restrict__ Wlo,
    const float* __restrict__ bias, float* __restrict__ C)
{
    extern __shared__ __align__(16) float sm[];

    const int tid  = threadIdx.x;
    const int lane = tid & 31;
    const int w    = tid >> 5;
    const int gid  = lane >> 2;
    const int tig  = lane & 3;
    const int wm0  = (w >> 2) * 64;   // warp m offset in tile
    const int wn0  = (w & 3) * 32;    // warp n offset in tile
    const int m0   = blockIdx.y * TBM;
    const int n0   = blockIdx.x * TBN;

    float acc[4][4][4];
    #pragma unroll
    for (int mf = 0; mf < 4; mf++)
        #pragma unroll
        for (int nf = 0; nf < 4; nf++)
            #pragma unroll
            for (int r = 0; r < 4; r++) acc[mf][nf][r] = 0.f;

    auto load_tiles = [&](int it, int buf) {
        int k0 = it * TBK;
        #pragma unroll
        for (int j = 0; j < 2; j++) {
            int c = tid + 256 * j;
            int row = c >> 2, seg = c & 3;
            size_t goff = (size_t)(m0 + row) * DQ + k0 + seg * 4;
            int soff = buf * AS_TILE + row * AS_STRIDE + seg * 4;
            uint32_t d0 = (uint32_t)__cvta_generic_to_shared(&sm[OFF_ASH + soff]);
            uint32_t d1 = (uint32_t)__cvta_generic_to_shared(&sm[OFF_ASL + soff]);
            asm volatile("cp.async.ca.shared.global [%0], [%1], 16;" :: "r"(d0), "l"(Ahi + goff));
            asm volatile("cp.async.ca.shared.global [%0], [%1], 16;" :: "r"(d1), "l"(Alo + goff));
        }
        #pragma unroll
        for (int j = 0; j < 2; j++) {
            int c = tid + 256 * j;
            int k = c >> 5, seg = c & 31;
            size_t goff = (size_t)(k0 + k) * DQ + n0 + seg * 4;
            int soff = buf * BS_TILE + k * BS_STRIDE + seg * 4;
            uint32_t d0 = (uint32_t)__cvta_generic_to_shared(&sm[OFF_BSH + soff]);
            uint32_t d1 = (uint32_t)__cvta_generic_to_shared(&sm[OFF_BSL + soff]);
            asm volatile("cp.async.ca.shared.global [%0], [%1], 16;" :: "r"(d0), "l"(Whi + goff));
            asm volatile("cp.async.ca.shared.global [%0], [%1], 16;" :: "r"(d1), "l"(Wlo + goff));
        }
        asm volatile("cp.async.commit_group;");
    };

    load_tiles(0, 0);

    const int NIT = DQ / TBK;   // 64
    for (int it = 0; it < NIT; it++) {
        int buf = it & 1;
        if (it + 1 < NIT) {
            load_tiles(it + 1, buf ^ 1);
            asm volatile("cp.async.wait_group 1;");
        } else {
            asm volatile("cp.async.wait_group 0;");
        }
        __syncthreads();

        #pragma unroll
        for (int ks = 0; ks < 2; ks++) {
            int kk = ks * 8;
            uint32_t ah[4][4], al[4][4];
            #pragma unroll
            for (int mf = 0; mf < 4; mf++) {
                int r = wm0 + mf * 16;
                int i00 = buf * AS_TILE + (r + gid) * AS_STRIDE + kk + tig;
                int i01 = buf * AS_TILE + (r + gid + 8) * AS_STRIDE + kk + tig;
                ah[mf][0] = __float_as_uint(sm[OFF_ASH + i00]);
                ah[mf][1] = __float_as_uint(sm[OFF_ASH + i01]);
                ah[mf][2] = __float_as_uint(sm[OFF_ASH + i00 + 4]);
                ah[mf][3] = __float_as_uint(sm[OFF_ASH + i01 + 4]);
                al[mf][0] = __float_as_uint(sm[OFF_ASL + i00]);
                al[mf][1] = __float_as_uint(sm[OFF_ASL + i01]);
                al[mf][2] = __float_as_uint(sm[OFF_ASL + i00 + 4]);
                al[mf][3] = __float_as_uint(sm[OFF_ASL + i01 + 4]);
            }
            uint32_t bh[4][2], bl[4][2];
            #pragma unroll
            for (int nf = 0; nf < 4; nf++) {
                int cN = wn0 + nf * 8 + gid;
                int i0 = buf * BS_TILE + (kk + tig) * BS_STRIDE + cN;
                int i1 = buf * BS_TILE + (kk + tig + 4) * BS_STRIDE + cN;
                bh[nf][0] = __float_as_uint(sm[OFF_BSH + i0]);
                bh[nf][1] = __float_as_uint(sm[OFF_BSH + i1]);
                bl[nf][0] = __float_as_uint(sm[OFF_BSL + i0]);
                bl[nf][1] = __float_as_uint(sm[OFF_BSL + i1]);
            }
            #pragma unroll
            for (int mf = 0; mf < 4; mf++)
                #pragma unroll
                for (int nf = 0; nf < 4; nf++) {
                    mma_tf32(acc[mf][nf], ah[mf][0], ah[mf][1], ah[mf][2], ah[mf][3],
                             bh[nf][0], bh[nf][1]);
                    mma_tf32(acc[mf][nf], al[mf][0], al[mf][1], al[mf][2], al[mf][3],
                             bh[nf][0], bh[nf][1]);
                    mma_tf32(acc[mf][nf], ah[mf][0], ah[mf][1], ah[mf][2], ah[mf][3],
                             bl[nf][0], bl[nf][1]);
                }
        }
        __syncthreads();
    }

    // epilogue: bias + store (c0,c1 adjacent cols -> float2)
    #pragma unroll
    for (int mf = 0; mf < 4; mf++) {
        #pragma unroll
        for (int nf = 0; nf < 4; nf++) {
            int r0 = m0 + wm0 + mf * 16 + gid;
            int cN = n0 + wn0 + nf * 8 + 2 * tig;
            float2 bv = *(const float2*)(bias + cN);
            float2 o0 = make_float2(acc[mf][nf][0] + bv.x, acc[mf][nf][1] + bv.y);
            float2 o1 = make_float2(acc[mf][nf][2] + bv.x, acc[mf][nf][3] + bv.y);
            *(float2*)(C + (size_t)r0 * DQ + cN) = o0;
            *(float2*)(C + (size_t)(r0 + 8) * DQ + cN) = o1;
        }
    }
}

// ---------------- persistent scan kernel (tf32 mma) ----------------
#define NB_SCAN 128
// SMEM: Bfrag 128 ksteps * 2 nfrags * 32 lanes * 8B = 64 KB, partials 8*64*16*4 = 32 KB
#define SCAN_SMEM_BYTES (65536 + 32768)

// acquire/release grid barrier (no MEMBAR, no volatile spin)
__device__ __forceinline__ void grid_sync()
{
    __syncthreads();
    if (threadIdx.x == 0) {
        unsigned gen;
        asm volatile("ld.acquire.gpu.global.u32 %0, [%1];"
                     : "=r"(gen) : "l"(&g_bar_gen));
        unsigned arrived;
        asm volatile("atom.release.gpu.global.add.u32 %0, [%1], %2;"
                     : "=r"(arrived) : "l"(&g_bar_count), "r"(1u));
        if (arrived == NB_SCAN - 1) {
            asm volatile("st.relaxed.gpu.global.u32 [%0], %1;"
                         :: "l"(&g_bar_count), "r"(0u));
            asm volatile("st.release.gpu.global.u32 [%0], %1;"
                         :: "l"(&g_bar_gen), "r"(gen + 1));
        } else {
            unsigned cur;
            do {
                asm volatile("ld.acquire.gpu.global.u32 %0, [%1];"
                             : "=r"(cur) : "l"(&g_bar_gen));
            } while (cur == gen);
        }
    }
    __syncthreads();
}

__global__ __launch_bounds__(256) void scan_kernel(
    const float* __restrict__ x,  const float* __restrict__ xi,
    const float* __restrict__ xf, const float* __restrict__ xc,
    const float* __restrict__ Wic, const float* __restrict__ Wfc,
    float* __restrict__ cbuf,     // [2][BQ*DQ]
    float* __restrict__ h, int reverse)
{
    extern __shared__ __align__(16) char smem_raw[];
    uint2* Bs   = (uint2*)smem_raw;                  // [128 ksteps][2 nf][32 lanes]
    float* part = (float*)(smem_raw + 65536);        // [8 warps][64 b][16 cols]

    const int tid  = threadIdx.x;
    const int lane = tid & 31;
    const int w    = tid >> 5;
    const int gid  = lane >> 2;       // groupID 0..7
    const int tig  = lane & 3;        // threadID in group
    const int n0   = blockIdx.x * 8;  // this CTA's output column base

    // ---- pre-lay weights in fragment order, tf32-converted (once per scan) ----
    for (int idx = tid; idx < 128 * 2 * 32; idx += 256) {
        int l  = idx & 31;
        int nf = (idx >> 5) & 1;
        int ks = idx >> 6;
        int kg = ks * 8 + 2 * (l & 3);
        int col = n0 + (l >> 2);
        const float* M = nf ? Wfc : Wic;
        uint2 v;
        v.x = f32_to_tf32(M[(size_t)kg * DQ + col]);
        v.y = f32_to_tf32(M[(size_t)(kg + 1) * DQ + col]);
        Bs[idx] = v;
    }
    __syncthreads();

    const int ks0 = w * 16;   // warp's k-step range

    // tail addressing (constant across steps except t)
    int bbs[2], gns[2];
    #pragma unroll
    for (int rep = 0; rep < 2; rep++) {
        int rr = tid + rep * 256;
        bbs[rep] = rr >> 3;
        gns[rep] = n0 + (rr & 7);
    }

    for (int step = 0; step < LQ; step++) {
        const int t = reverse ? (LQ - 1 - step) : step;
        const float* cprev = cbuf + (step & 1) * (BQ * DQ);
        float* cnext = cbuf + ((step + 1) & 1) * (BQ * DQ);

        // ---- prefetch tail operands early (DRAM latency hides under mma phase) --
        float t_xi[2], t_xf[2], t_xc[2], t_x[2], t_c[2];
        size_t offs[2];
        #pragma unroll
        for (int rep = 0; rep < 2; rep++) {
            size_t off = ((size_t)t * BQ + bbs[rep]) * DQ + gns[rep];
            offs[rep] = off;
            t_xi[rep] = __ldcg(xi + off);
            t_xf[rep] = __ldcg(xf + off);
            t_xc[rep] = __ldcg(xc + off);
            t_x[rep]  = __ldcg(x + off);
            t_c[rep]  = __ldcg(cprev + (size_t)bbs[rep] * DQ + gns[rep]);
        }

        float acc[4][2][4];
        #pragma unroll
        for (int m = 0; m < 4; m++)
            #pragma unroll
            for (int nf = 0; nf < 2; nf++)
                #pragma unroll
                for (int r = 0; r < 4; r++) acc[m][nf][r] = 0.f;

        #pragma unroll 4
        for (int ks = 0; ks < 16; ks++) {
            int kstep = ks0 + ks;
            uint2 bu = Bs[(kstep * 2 + 0) * 32 + lane];
            uint2 bv = Bs[(kstep * 2 + 1) * 32 + lane];
            int kg = kstep * 8 + 2 * tig;
            const float* abase = cprev + (size_t)gid * DQ + kg;
            // group all loads first (deep MLP), then mmas
            float2 av[8];
            #pragma unroll
            for (int m = 0; m < 4; m++) {
                av[2 * m]     = __ldcg((const float2*)(abase + (size_t)(m * 16) * DQ));
                av[2 * m + 1] = __ldcg((const float2*)(abase + (size_t)(m * 16 + 8) * DQ));
            }
            #pragma unroll
            for (int m = 0; m < 4; m++) {
                uint32_t a0 = f32_to_tf32(av[2 * m].x);
                uint32_t a2 = f32_to_tf32(av[2 * m].y);
                uint32_t a1 = f32_to_tf32(av[2 * m + 1].x);
                uint32_t a3 = f32_to_tf32(av[2 * m + 1].y);
                mma_tf32(acc[m][0], a0, a1, a2, a3, bu.x, bu.y);
                mma_tf32(acc[m][1], a0, a1, a2, a3, bv.x, bv.y);
            }
        }

        // ---- write split-K partials: part[w][b][col] ----
        #pragma unroll
        for (int m = 0; m < 4; m++) {
            #pragma unroll
            for (int nf = 0; nf < 2; nf++) {
                int col = nf * 8 + 2 * tig;
                int b0r = m * 16 + gid;
                float2* p0 = (float2*)&part[((w * 64) + b0r) * 16 + col];
                float2* p1 = (float2*)&part[((w * 64) + b0r + 8) * 16 + col];
                *p0 = make_float2(acc[m][nf][0], acc[m][nf][1]);
                *p1 = make_float2(acc[m][nf][2], acc[m][nf][3]);
            }
        }
        __syncthreads();

        // ---- reduce over warps + elementwise update: 64b x 8n, 2 per thread ----
        #pragma unroll
        for (int rep = 0; rep < 2; rep++) {
            int rr = tid + rep * 256;
            int bb = rr >> 3, nn = rr & 7;
            float uu = 0.f, vv = 0.f;
            #pragma unroll
            for (int ww = 0; ww < 8; ww++) {
                uu += part[((ww * 64) + bb) * 16 + nn];
                vv += part[((ww * 64) + bb) * 16 + 8 + nn];
            }
            float iv = 1.0f / (1.0f + expf(-(t_xi[rep] + uu)));
            float fv = 1.0f / (1.0f + expf(-(t_xf[rep] + vv)));
            float cn = iv * t_xc[rep] + fv * t_c[rep];
            cnext[(size_t)bb * DQ + gns[rep]] = cn;
            h[offs[rep]] = tanhf(cn) + t_x[rep];
        }
        grid_sync();
    }
}

// ---------------- launcher ----------------
extern "C" void kernel_launch(void* const* d_in, const int* in_sizes, int n_in,
                              void* d_out, int out_size)
{
    (void)in_sizes; (void)n_in; (void)out_size;

    cudaFuncSetAttribute(scan_kernel, cudaFuncAttributeMaxDynamicSharedMemorySize,
                         SCAN_SMEM_BYTES);
    cudaFuncSetAttribute(sgemm_presplit, cudaFuncAttributeMaxDynamicSharedMemorySize,
                         GEMM_SMEM_BYTES);

    const int*   xs  = (const int*)d_in[0];
    const float* emb = (const float*)d_in[1];
    const float* P[16];
    for (int i = 0; i < 16; i++) P[i] = (const float*)d_in[2 + i];
    // P: 0=fw_Wix 1=fw_Wic 2=fw_Wfx 3=fw_Wfc 4=fw_Wcx 5=fw_bi 6=fw_bf 7=fw_bc
    //    8=bw_Wix 9=bw_Wic 10=bw_Wfx 11=bw_Wfc 12=bw_Wcx 13=bw_bi 14=bw_bf 15=bw_bc

    float *px, *ph, *pxi, *pxf, *pxc, *pcb, *pahi, *palo, *pwhi, *pwlo;
    cudaGetSymbolAddress((void**)&px,   g_x);
    cudaGetSymbolAddress((void**)&ph,   g_h);
    cudaGetSymbolAddress((void**)&pxi,  g_xi);
    cudaGetSymbolAddress((void**)&pxf,  g_xf);
    cudaGetSymbolAddress((void**)&pxc,  g_xc);
    cudaGetSymbolAddress((void**)&pcb,  g_cbuf);
    cudaGetSymbolAddress((void**)&pahi, g_ahi);
    cudaGetSymbolAddress((void**)&palo, g_alo);
    cudaGetSymbolAddress((void**)&pwhi, g_whi);
    cudaGetSymbolAddress((void**)&pwlo, g_wlo);
    float* out = (float*)d_out;

    embed_kernel<<<MQ * DQ / 4 / 256, 256>>>(xs, emb, px);
    zero_kernel<<<(2 * BQ * DQ + 255) / 256, 256>>>(pcb, 2 * BQ * DQ);

    // pre-split the 6 input-projection weight matrices (once per launch)
    const int WN4 = DQ * DQ / 4;                // 262144
    const int widx[6] = {0, 2, 4, 8, 10, 12};   // Wix, Wfx, Wcx for fw then bw
    for (int j = 0; j < 6; j++) {
        split_kernel<<<WN4 / 256, 256>>>((const float4*)P[widx[j]],
                                         (float4*)(pwhi + (size_t)j * DQ * DQ),
                                         (float4*)(pwlo + (size_t)j * DQ * DQ), WN4);
    }

    const int AN4 = MQ * DQ / 4;                // 4M
    dim3 ggrid(DQ / TBN, MQ / TBM);             // (8, 128)
    for (int layer = 0; layer < 2; layer++) {
        // forward direction
        split_kernel<<<AN4 / 256, 256>>>((const float4*)px, (float4*)pahi, (float4*)palo, AN4);
        sgemm_presplit<<<ggrid, 256, GEMM_SMEM_BYTES>>>(pahi, palo,
            pwhi + 0 * (size_t)DQ * DQ, pwlo + 0 * (size_t)DQ * DQ, P[5], pxi);
        sgemm_presplit<<<ggrid, 256, GEMM_SMEM_BYTES>>>(pahi, palo,
            pwhi + 1 * (size_t)DQ * DQ, pwlo + 1 * (size_t)DQ * DQ, P[6], pxf);
        sgemm_presplit<<<ggrid, 256, GEMM_SMEM_BYTES>>>(pahi, palo,
            pwhi + 2 * (size_t)DQ * DQ, pwlo + 2 * (size_t)DQ * DQ, P[7], pxc);
        scan_kernel<<<NB_SCAN, 256, SCAN_SMEM_BYTES>>>(px, pxi, pxf, pxc,
                                                       P[1], P[3], pcb, ph, 0);
        // backward direction
        split_kernel<<<AN4 / 256, 256>>>((const float4*)ph, (float4*)pahi, (float4*)palo, AN4);
        sgemm_presplit<<<ggrid, 256, GEMM_SMEM_BYTES>>>(pahi, palo,
            pwhi + 3 * (size_t)DQ * DQ, pwlo + 3 * (size_t)DQ * DQ, P[13], pxi);
        sgemm_presplit<<<ggrid, 256, GEMM_SMEM_BYTES>>>(pahi, palo,
            pwhi + 4 * (size_t)DQ * DQ, pwlo + 4 * (size_t)DQ * DQ, P[14], pxf);
        sgemm_presplit<<<ggrid, 256, GEMM_SMEM_BYTES>>>(pahi, palo,
            pwhi + 5 * (size_t)DQ * DQ, pwlo + 5 * (size_t)DQ * DQ, P[15], pxc);
        float* ho = (layer == 1) ? out : px;
        scan_kernel<<<NB_SCAN, 256, SCAN_SMEM_BYTES>>>(ph, pxi, pxf, pxc,
                                                       P[9], P[11], pcb, ho, 1);
    }
}

// round 8
// speedup vs baseline: 2.7345x; 1.1296x over previous
#include <cuda_runtime.h>
#include <math.h>
#include <stdint.h>

#define LQ 256
#define BQ 64
#define DQ 1024
#define VQ 32000
#define MQ (LQ * BQ)          // 16384 rows for projections
#define NB_SCAN 128

// ---------------- scratch (static device globals; no allocation) ----------------
__device__ float g_x [LQ * BQ * DQ];   // current layer input / bw output
__device__ float g_h [LQ * BQ * DQ];   // fw output ("first")
__device__ float g_xi[LQ * BQ * DQ];
__device__ float g_xf[LQ * BQ * DQ];
__device__ float g_xc[LQ * BQ * DQ];
__device__ float g_cbuf[2 * BQ * DQ];  // double-buffered recurrent state
__device__ float g_ahi[LQ * BQ * DQ];  // pre-split GEMM A operand (hi)
__device__ float g_alo[LQ * BQ * DQ];  // pre-split GEMM A operand (lo)
__device__ float g_whi[6 * DQ * DQ];   // pre-split weights (hi)
__device__ float g_wlo[6 * DQ * DQ];   // pre-split weights (lo)
__device__ unsigned g_flags[NB_SCAN + 1];  // per-CTA arrival flags + go word

// ---------------- embedding gather ----------------
__global__ __launch_bounds__(256) void embed_kernel(
    const int* __restrict__ xs, const float* __restrict__ emb, float* __restrict__ x)
{
    int i = blockIdx.x * 256 + threadIdx.x;     // over MQ*DQ/4 float4's
    int tokpos = i >> 8;                        // DQ/4 = 256 float4 per row
    int d4 = i & 255;
    int tok = xs[tokpos];
    tok = min(max(tok, 0), VQ - 1);
    ((float4*)x)[i] = ((const float4*)(emb + (size_t)tok * DQ))[d4];
}

__global__ __launch_bounds__(256) void zero_kernel(float* __restrict__ p, int n)
{
    int i = blockIdx.x * 256 + threadIdx.x;
    if (i < n) p[i] = 0.0f;
}

// ---------------- tf32 helpers ----------------
__device__ __forceinline__ uint32_t f32_to_tf32(float f)
{
    uint32_t u;
    asm("cvt.rna.tf32.f32 %0, %1;" : "=r"(u) : "f"(f));
    return u;
}

__device__ __forceinline__ float tf32r(float f)
{
    uint32_t u;
    asm("cvt.rna.tf32.f32 %0, %1;" : "=r"(u) : "f"(f));
    return __uint_as_float(u);
}

__device__ __forceinline__ void mma_tf32(float d[4],
    uint32_t a0, uint32_t a1, uint32_t a2, uint32_t a3,
    uint32_t b0, uint32_t b1)
{
    asm volatile(
        "mma.sync.aligned.m16n8k8.row.col.f32.tf32.tf32.f32 "
        "{%0,%1,%2,%3}, {%4,%5,%6,%7}, {%8,%9}, {%0,%1,%2,%3};"
        : "+f"(d[0]), "+f"(d[1]), "+f"(d[2]), "+f"(d[3])
        : "r"(a0), "r"(a1), "r"(a2), "r"(a3), "r"(b0), "r"(b1));
}

// ---------------- hi/lo split kernel (RNA tf32 decomposition) ----------------
__global__ __launch_bounds__(256) void split_kernel(
    const float4* __restrict__ src, float4* __restrict__ hi, float4* __restrict__ lo, int n4)
{
    int i = blockIdx.x * 256 + threadIdx.x;
    if (i >= n4) return;
    float4 v = src[i];
    float4 h, l;
    h.x = tf32r(v.x); l.x = tf32r(v.x - h.x);
    h.y = tf32r(v.y); l.y = tf32r(v.y - h.y);
    h.z = tf32r(v.z); l.z = tf32r(v.z - h.z);
    h.w = tf32r(v.w); l.w = tf32r(v.w - h.w);
    hi[i] = h;
    lo[i] = l;
}

// ---------------- 3xTF32 pre-split GEMM + bias: C = A@W + bias ----------------
#define TBM 128
#define TBN 128
#define TBK 16
#define APAD 4
#define BPAD 4
#define AS_STRIDE (TBK + APAD)          // 20
#define BS_STRIDE (TBN + BPAD)          // 132
#define AS_TILE (TBM * AS_STRIDE)       // 2560 floats per buf
#define BS_TILE (TBK * BS_STRIDE)       // 2112 floats per buf
#define OFF_ASH 0
#define OFF_ASL (2 * AS_TILE)
#define OFF_BSH (4 * AS_TILE)
#define OFF_BSL (4 * AS_TILE + 2 * BS_TILE)
#define GEMM_SMEM_BYTES ((4 * AS_TILE + 4 * BS_TILE) * 4)   // 74752

__global__ __launch_bounds__(256) void sgemm_presplit(
    const float* __restrict__ Ahi, const float* __restrict__ Alo,
    const float* __restrict__ Whi, const float* __restrict__ Wlo,
    const float* __restrict__ bias, float* __restrict__ C)
{
    extern __shared__ __align__(16) float sm[];

    const int tid  = threadIdx.x;
    const int lane = tid & 31;
    const int w    = tid >> 5;
    const int gid  = lane >> 2;
    const int tig  = lane & 3;
    const int wm0  = (w >> 2) * 64;   // warp m offset in tile
    const int wn0  = (w & 3) * 32;    // warp n offset in tile
    const int m0   = blockIdx.y * TBM;
    const int n0   = blockIdx.x * TBN;

    float acc[4][4][4];
    #pragma unroll
    for (int mf = 0; mf < 4; mf++)
        #pragma unroll
        for (int nf = 0; nf < 4; nf++)
            #pragma unroll
            for (int r = 0; r < 4; r++) acc[mf][nf][r] = 0.f;

    auto load_tiles = [&](int it, int buf) {
        int k0 = it * TBK;
        #pragma unroll
        for (int j = 0; j < 2; j++) {
            int c = tid + 256 * j;
            int row = c >> 2, seg = c & 3;
            size_t goff = (size_t)(m0 + row) * DQ + k0 + seg * 4;
            int soff = buf * AS_TILE + row * AS_STRIDE + seg * 4;
            uint32_t d0 = (uint32_t)__cvta_generic_to_shared(&sm[OFF_ASH + soff]);
            uint32_t d1 = (uint32_t)__cvta_generic_to_shared(&sm[OFF_ASL + soff]);
            asm volatile("cp.async.ca.shared.global [%0], [%1], 16;" :: "r"(d0), "l"(Ahi + goff));
            asm volatile("cp.async.ca.shared.global [%0], [%1], 16;" :: "r"(d1), "l"(Alo + goff));
        }
        #pragma unroll
        for (int j = 0; j < 2; j++) {
            int c = tid + 256 * j;
            int k = c >> 5, seg = c & 31;
            size_t goff = (size_t)(k0 + k) * DQ + n0 + seg * 4;
            int soff = buf * BS_TILE + k * BS_STRIDE + seg * 4;
            uint32_t d0 = (uint32_t)__cvta_generic_to_shared(&sm[OFF_BSH + soff]);
            uint32_t d1 = (uint32_t)__cvta_generic_to_shared(&sm[OFF_BSL + soff]);
            asm volatile("cp.async.ca.shared.global [%0], [%1], 16;" :: "r"(d0), "l"(Whi + goff));
            asm volatile("cp.async.ca.shared.global [%0], [%1], 16;" :: "r"(d1), "l"(Wlo + goff));
        }
        asm volatile("cp.async.commit_group;");
    };

    load_tiles(0, 0);

    const int NIT = DQ / TBK;   // 64
    for (int it = 0; it < NIT; it++) {
        int buf = it & 1;
        if (it + 1 < NIT) {
            load_tiles(it + 1, buf ^ 1);
            asm volatile("cp.async.wait_group 1;");
        } else {
            asm volatile("cp.async.wait_group 0;");
        }
        __syncthreads();

        #pragma unroll
        for (int ks = 0; ks < 2; ks++) {
            int kk = ks * 8;
            uint32_t ah[4][4], al[4][4];
            #pragma unroll
            for (int mf = 0; mf < 4; mf++) {
                int r = wm0 + mf * 16;
                int i00 = buf * AS_TILE + (r + gid) * AS_STRIDE + kk + tig;
                int i01 = buf * AS_TILE + (r + gid + 8) * AS_STRIDE + kk + tig;
                ah[mf][0] = __float_as_uint(sm[OFF_ASH + i00]);
                ah[mf][1] = __float_as_uint(sm[OFF_ASH + i01]);
                ah[mf][2] = __float_as_uint(sm[OFF_ASH + i00 + 4]);
                ah[mf][3] = __float_as_uint(sm[OFF_ASH + i01 + 4]);
                al[mf][0] = __float_as_uint(sm[OFF_ASL + i00]);
                al[mf][1] = __float_as_uint(sm[OFF_ASL + i01]);
                al[mf][2] = __float_as_uint(sm[OFF_ASL + i00 + 4]);
                al[mf][3] = __float_as_uint(sm[OFF_ASL + i01 + 4]);
            }
            uint32_t bh[4][2], bl[4][2];
            #pragma unroll
            for (int nf = 0; nf < 4; nf++) {
                int cN = wn0 + nf * 8 + gid;
                int i0 = buf * BS_TILE + (kk + tig) * BS_STRIDE + cN;
                int i1 = buf * BS_TILE + (kk + tig + 4) * BS_STRIDE + cN;
                bh[nf][0] = __float_as_uint(sm[OFF_BSH + i0]);
                bh[nf][1] = __float_as_uint(sm[OFF_BSH + i1]);
                bl[nf][0] = __float_as_uint(sm[OFF_BSL + i0]);
                bl[nf][1] = __float_as_uint(sm[OFF_BSL + i1]);
            }
            #pragma unroll
            for (int mf = 0; mf < 4; mf++)
                #pragma unroll
                for (int nf = 0; nf < 4; nf++) {
                    mma_tf32(acc[mf][nf], ah[mf][0], ah[mf][1], ah[mf][2], ah[mf][3],
                             bh[nf][0], bh[nf][1]);
                    mma_tf32(acc[mf][nf], al[mf][0], al[mf][1], al[mf][2], al[mf][3],
                             bh[nf][0], bh[nf][1]);
                    mma_tf32(acc[mf][nf], ah[mf][0], ah[mf][1], ah[mf][2], ah[mf][3],
                             bl[nf][0], bl[nf][1]);
                }
        }
        __syncthreads();
    }

    #pragma unroll
    for (int mf = 0; mf < 4; mf++) {
        #pragma unroll
        for (int nf = 0; nf < 4; nf++) {
            int r0 = m0 + wm0 + mf * 16 + gid;
            int cN = n0 + wn0 + nf * 8 + 2 * tig;
            float2 bv = *(const float2*)(bias + cN);
            float2 o0 = make_float2(acc[mf][nf][0] + bv.x, acc[mf][nf][1] + bv.y);
            float2 o1 = make_float2(acc[mf][nf][2] + bv.x, acc[mf][nf][3] + bv.y);
            *(float2*)(C + (size_t)r0 * DQ + cN) = o0;
            *(float2*)(C + (size_t)(r0 + 8) * DQ + cN) = o1;
        }
    }
}

// ---------------- persistent scan kernel (tf32 mma) ----------------
// SMEM: Bfrag 64 blocks * 2 subs * 2 nf * 32 lanes * 8B = 64 KB, partials 32 KB
#define SCAN_SMEM_BYTES (65536 + 32768)

__global__ __launch_bounds__(256) void scan_kernel(
    const float* __restrict__ x,  const float* __restrict__ xi,
    const float* __restrict__ xf, const float* __restrict__ xc,
    const float* __restrict__ Wic, const float* __restrict__ Wfc,
    float* __restrict__ cbuf,     // [2][BQ*DQ]
    float* __restrict__ h, int reverse, int epoch)
{
    extern __shared__ __align__(16) char smem_raw[];
    uint2* Bs   = (uint2*)smem_raw;                  // [64 blk][2 sub][2 nf][32 lanes]
    float* part = (float*)(smem_raw + 65536);        // [8 warps][64 b][16 cols]

    const int tid  = threadIdx.x;
    const int lane = tid & 31;
    const int w    = tid >> 5;
    const int gid  = lane >> 2;       // groupID 0..7
    const int tig  = lane & 3;        // threadID in group
    const int n0   = blockIdx.x * 8;  // this CTA's output column base
    const int bid  = blockIdx.x;

    // ---- pre-lay weights in fragment order, tf32-converted (once per scan) ----
    // Index [blk][sub][nf][lane]. k-permutation: within a 16-k block, lane tig
    // owns k = 4*tig..4*tig+3; sub s uses (4*tig+2s, 4*tig+2s+1).
    for (int idx = tid; idx < 64 * 2 * 2 * 32; idx += 256) {
        int l   = idx & 31;
        int nf  = (idx >> 5) & 1;
        int sub = (idx >> 6) & 1;
        int blk = idx >> 7;
        int kg  = blk * 16 + 4 * (l & 3) + 2 * sub;
        int col = n0 + (l >> 2);
        const float* M = nf ? Wfc : Wic;
        uint2 v;
        v.x = f32_to_tf32(M[(size_t)kg * DQ + col]);
        v.y = f32_to_tf32(M[(size_t)(kg + 1) * DQ + col]);
        Bs[idx] = v;
    }
    __syncthreads();

    const int blk0 = w * 8;   // warp's 8 16-k blocks (k range [w*128, w*128+128))

    // tail addressing (constant across steps except t)
    int bbs[2], gns[2];
    #pragma unroll
    for (int rep = 0; rep < 2; rep++) {
        int rr = tid + rep * 256;
        bbs[rep] = rr >> 3;
        gns[rep] = n0 + (rr & 7);
    }

    for (int step = 0; step < LQ; step++) {
        const int t = reverse ? (LQ - 1 - step) : step;
        const float* cprev = cbuf + (step & 1) * (BQ * DQ);
        float* cnext = cbuf + ((step + 1) & 1) * (BQ * DQ);

        // ---- prefetch tail operands early ----
        float t_xi[2], t_xf[2], t_xc[2], t_x[2], t_c[2];
        size_t offs[2];
        #pragma unroll
        for (int rep = 0; rep < 2; rep++) {
            size_t off = ((size_t)t * BQ + bbs[rep]) * DQ + gns[rep];
            offs[rep] = off;
            t_xi[rep] = __ldcg(xi + off);
            t_xf[rep] = __ldcg(xf + off);
            t_xc[rep] = __ldcg(xc + off);
            t_x[rep]  = __ldcg(x + off);
            t_c[rep]  = __ldcg(cprev + (size_t)bbs[rep] * DQ + gns[rep]);
        }

        float acc[4][2][4];
        #pragma unroll
        for (int m = 0; m < 4; m++)
            #pragma unroll
            for (int nf = 0; nf < 2; nf++)
                #pragma unroll
                for (int r = 0; r < 4; r++) acc[m][nf][r] = 0.f;

        #pragma unroll 2
        for (int j = 0; j < 8; j++) {
            int blk = blk0 + j;
            uint2 bu0 = Bs[((blk * 2 + 0) * 2 + 0) * 32 + lane];
            uint2 bv0 = Bs[((blk * 2 + 0) * 2 + 1) * 32 + lane];
            uint2 bu1 = Bs[((blk * 2 + 1) * 2 + 0) * 32 + lane];
            uint2 bv1 = Bs[((blk * 2 + 1) * 2 + 1) * 32 + lane];
            int kg = blk * 16 + 4 * tig;
            const float* abase = cprev + (size_t)gid * DQ + kg;
            // one float4 per row covers both sub-ksteps (deep MLP: all loads first)
            float4 av[8];
            #pragma unroll
            for (int m = 0; m < 4; m++) {
                av[2 * m]     = __ldcg((const float4*)(abase + (size_t)(m * 16) * DQ));
                av[2 * m + 1] = __ldcg((const float4*)(abase + (size_t)(m * 16 + 8) * DQ));
            }
            #pragma unroll
            for (int m = 0; m < 4; m++) {
                // sub 0: k = 4tig, 4tig+1
                uint32_t a0 = f32_to_tf32(av[2 * m].x);
                uint32_t a2 = f32_to_tf32(av[2 * m].y);
                uint32_t a1 = f32_to_tf32(av[2 * m + 1].x);
                uint32_t a3 = f32_to_tf32(av[2 * m + 1].y);
                mma_tf32(acc[m][0], a0, a1, a2, a3, bu0.x, bu0.y);
                mma_tf32(acc[m][1], a0, a1, a2, a3, bv0.x, bv0.y);
                // sub 1: k = 4tig+2, 4tig+3
                uint32_t c0 = f32_to_tf32(av[2 * m].z);
                uint32_t c2 = f32_to_tf32(av[2 * m].w);
                uint32_t c1 = f32_to_tf32(av[2 * m + 1].z);
                uint32_t c3 = f32_to_tf32(av[2 * m + 1].w);
                mma_tf32(acc[m][0], c0, c1, c2, c3, bu1.x, bu1.y);
                mma_tf32(acc[m][1], c0, c1, c2, c3, bv1.x, bv1.y);
            }
        }

        // ---- write split-K partials: part[w][b][col] ----
        #pragma unroll
        for (int m = 0; m < 4; m++) {
            #pragma unroll
            for (int nf = 0; nf < 2; nf++) {
                int col = nf * 8 + 2 * tig;
                int b0r = m * 16 + gid;
                float2* p0 = (float2*)&part[((w * 64) + b0r) * 16 + col];
                float2* p1 = (float2*)&part[((w * 64) + b0r + 8) * 16 + col];
                *p0 = make_float2(acc[m][nf][0], acc[m][nf][1]);
                *p1 = make_float2(acc[m][nf][2], acc[m][nf][3]);
            }
        }
        __syncthreads();

        // ---- reduce over warps + elementwise update: 64b x 8n, 2 per thread ----
        #pragma unroll
        for (int rep = 0; rep < 2; rep++) {
            int rr = tid + rep * 256;
            int bb = rr >> 3, nn = rr & 7;
            float uu = 0.f, vv = 0.f;
            #pragma unroll
            for (int ww = 0; ww < 8; ww++) {
                uu += part[((ww * 64) + bb) * 16 + nn];
                vv += part[((ww * 64) + bb) * 16 + 8 + nn];
            }
            float iv = 1.0f / (1.0f + expf(-(t_xi[rep] + uu)));
            float fv = 1.0f / (1.0f + expf(-(t_xf[rep] + vv)));
            float cn = iv * t_xc[rep] + fv * t_c[rep];
            cnext[(size_t)bb * DQ + gns[rep]] = cn;
            h[offs[rep]] = tanhf(cn) + t_x[rep];
        }

        // ---- distributed flag barrier (parallel arrivals, no atomic chain) ----
        {
            const unsigned val = (unsigned)(epoch + step + 1);
            __syncthreads();
            if (tid == 0)
                asm volatile("st.release.gpu.global.u32 [%0], %1;"
                             :: "l"(g_flags + bid), "r"(val) : "memory");
            if (bid == 0) {
                if (tid < NB_SCAN) {
                    unsigned v;
                    do {
                        asm volatile("ld.acquire.gpu.global.u32 %0, [%1];"
                                     : "=r"(v) : "l"(g_flags + tid) : "memory");
                    } while (v < val);
                }
                __syncthreads();
                if (tid == 0)
                    asm volatile("st.release.gpu.global.u32 [%0], %1;"
                                 :: "l"(g_flags + NB_SCAN), "r"(val) : "memory");
            } else {
                if (tid == 0) {
                    unsigned v;
                    do {
                        asm volatile("ld.acquire.gpu.global.u32 %0, [%1];"
                                     : "=r"(v) : "l"(g_flags + NB_SCAN) : "memory");
                    } while (v < val);
                }
            }
            __syncthreads();
        }
    }
}

// ---------------- launcher ----------------
extern "C" void kernel_launch(void* const* d_in, const int* in_sizes, int n_in,
                              void* d_out, int out_size)
{
    (void)in_sizes; (void)n_in; (void)out_size;

    cudaFuncSetAttribute(scan_kernel, cudaFuncAttributeMaxDynamicSharedMemorySize,
                         SCAN_SMEM_BYTES);
    cudaFuncSetAttribute(sgemm_presplit, cudaFuncAttributeMaxDynamicSharedMemorySize,
                         GEMM_SMEM_BYTES);

    const int*   xs  = (const int*)d_in[0];
    const float* emb = (const float*)d_in[1];
    const float* P[16];
    for (int i = 0; i < 16; i++) P[i] = (const float*)d_in[2 + i];
    // P: 0=fw_Wix 1=fw_Wic 2=fw_Wfx 3=fw_Wfc 4=fw_Wcx 5=fw_bi 6=fw_bf 7=fw_bc
    //    8=bw_Wix 9=bw_Wic 10=bw_Wfx 11=bw_Wfc 12=bw_Wcx 13=bw_bi 14=bw_bf 15=bw_bc

    float *px, *ph, *pxi, *pxf, *pxc, *pcb, *pahi, *palo, *pwhi, *pwlo;
    unsigned* pflags;
    cudaGetSymbolAddress((void**)&px,    g_x);
    cudaGetSymbolAddress((void**)&ph,    g_h);
    cudaGetSymbolAddress((void**)&pxi,   g_xi);
    cudaGetSymbolAddress((void**)&pxf,   g_xf);
    cudaGetSymbolAddress((void**)&pxc,   g_xc);
    cudaGetSymbolAddress((void**)&pcb,   g_cbuf);
    cudaGetSymbolAddress((void**)&pahi,  g_ahi);
    cudaGetSymbolAddress((void**)&palo,  g_alo);
    cudaGetSymbolAddress((void**)&pwhi,  g_whi);
    cudaGetSymbolAddress((void**)&pwlo,  g_wlo);
    cudaGetSymbolAddress((void**)&pflags, g_flags);
    float* out = (float*)d_out;

    embed_kernel<<<MQ * DQ / 4 / 256, 256>>>(xs, emb, px);
    zero_kernel<<<(2 * BQ * DQ + 255) / 256, 256>>>(pcb, 2 * BQ * DQ);
    zero_kernel<<<1, 256>>>((float*)pflags, NB_SCAN + 1);

    // pre-split the 6 input-projection weight matrices (once per launch)
    const int WN4 = DQ * DQ / 4;                // 262144
    const int widx[6] = {0, 2, 4, 8, 10, 12};   // Wix, Wfx, Wcx for fw then bw
    for (int j = 0; j < 6; j++) {
        split_kernel<<<WN4 / 256, 256>>>((const float4*)P[widx[j]],
                                         (float4*)(pwhi + (size_t)j * DQ * DQ),
                                         (float4*)(pwlo + (size_t)j * DQ * DQ), WN4);
    }

    const int AN4 = MQ * DQ / 4;                // 4M
    dim3 ggrid(DQ / TBN, MQ / TBM);             // (8, 128)
    for (int layer = 0; layer < 2; layer++) {
        // forward direction
        split_kernel<<<AN4 / 256, 256>>>((const float4*)px, (float4*)pahi, (float4*)palo, AN4);
        sgemm_presplit<<<ggrid, 256, GEMM_SMEM_BYTES>>>(pahi, palo,
            pwhi + 0 * (size_t)DQ * DQ, pwlo + 0 * (size_t)DQ * DQ, P[5], pxi);
        sgemm_presplit<<<ggrid, 256, GEMM_SMEM_BYTES>>>(pahi, palo,
            pwhi + 1 * (size_t)DQ * DQ, pwlo + 1 * (size_t)DQ * DQ, P[6], pxf);
        sgemm_presplit<<<ggrid, 256, GEMM_SMEM_BYTES>>>(pahi, palo,
            pwhi + 2 * (size_t)DQ * DQ, pwlo + 2 * (size_t)DQ * DQ, P[7], pxc);
        scan_kernel<<<NB_SCAN, 256, SCAN_SMEM_BYTES>>>(px, pxi, pxf, pxc,
            P[1], P[3], pcb, ph, 0, (layer * 2 + 0) * LQ);
        // backward direction
        split_kernel<<<AN4 / 256, 256>>>((const float4*)ph, (float4*)pahi, (float4*)palo, AN4);
        sgemm_presplit<<<ggrid, 256, GEMM_SMEM_BYTES>>>(pahi, palo,
            pwhi + 3 * (size_t)DQ * DQ, pwlo + 3 * (size_t)DQ * DQ, P[13], pxi);
        sgemm_presplit<<<ggrid, 256, GEMM_SMEM_BYTES>>>(pahi, palo,
            pwhi + 4 * (size_t)DQ * DQ, pwlo + 4 * (size_t)DQ * DQ, P[14], pxf);
        sgemm_presplit<<<ggrid, 256, GEMM_SMEM_BYTES>>>(pahi, palo,
            pwhi + 5 * (size_t)DQ * DQ, pwlo + 5 * (size_t)DQ * DQ, P[15], pxc);
        float* ho = (layer == 1) ? out : px;
        scan_kernel<<<NB_SCAN, 256, SCAN_SMEM_BYTES>>>(ph, pxi, pxf, pxc,
            P[9], P[11], pcb, ho, 1, (layer * 2 + 1) * LQ);
    }
}

// round 9
// speedup vs baseline: 3.2905x; 1.2033x over previous
#include <cuda_runtime.h>
#include <cuda_bf16.h>
#include <math.h>
#include <stdint.h>

#define LQ 256
#define BQ 64
#define DQ 1024
#define VQ 32000
#define MQ (LQ * BQ)          // 16384 rows for projections
#define NB_SCAN 128

// ---------------- scratch (static device globals; no allocation) ----------------
__device__ float g_x [LQ * BQ * DQ];   // current layer input / bw output
__device__ float g_h [LQ * BQ * DQ];   // fw output ("first")
__device__ float g_xi[LQ * BQ * DQ];
__device__ float g_xf[LQ * BQ * DQ];
__device__ float g_xc[LQ * BQ * DQ];
__device__ float g_cbuf[2 * BQ * DQ];            // double-buffered recurrent state (fp32)
__device__ __nv_bfloat16 g_cbf[2 * BQ * DQ];     // bf16 shadow of c for mma loads
__device__ float g_ahi[LQ * BQ * DQ];  // pre-split GEMM A operand (hi)
__device__ float g_alo[LQ * BQ * DQ];  // pre-split GEMM A operand (lo)
__device__ float g_whi[6 * DQ * DQ];   // pre-split weights (hi)
__device__ float g_wlo[6 * DQ * DQ];   // pre-split weights (lo)
__device__ unsigned g_flags[NB_SCAN + 1];  // per-CTA arrival flags + go word

// ---------------- embedding gather ----------------
__global__ __launch_bounds__(256) void embed_kernel(
    const int* __restrict__ xs, const float* __restrict__ emb, float* __restrict__ x)
{
    int i = blockIdx.x * 256 + threadIdx.x;     // over MQ*DQ/4 float4's
    int tokpos = i >> 8;                        // DQ/4 = 256 float4 per row
    int d4 = i & 255;
    int tok = xs[tokpos];
    tok = min(max(tok, 0), VQ - 1);
    ((float4*)x)[i] = ((const float4*)(emb + (size_t)tok * DQ))[d4];
}

__global__ __launch_bounds__(256) void zero_kernel(float* __restrict__ p, int n)
{
    int i = blockIdx.x * 256 + threadIdx.x;
    if (i < n) p[i] = 0.0f;
}

// ---------------- tf32 helpers ----------------
__device__ __forceinline__ float tf32r(float f)
{
    uint32_t u;
    asm("cvt.rna.tf32.f32 %0, %1;" : "=r"(u) : "f"(f));
    return __uint_as_float(u);
}

__device__ __forceinline__ void mma_tf32(float d[4],
    uint32_t a0, uint32_t a1, uint32_t a2, uint32_t a3,
    uint32_t b0, uint32_t b1)
{
    asm volatile(
        "mma.sync.aligned.m16n8k8.row.col.f32.tf32.tf32.f32 "
        "{%0,%1,%2,%3}, {%4,%5,%6,%7}, {%8,%9}, {%0,%1,%2,%3};"
        : "+f"(d[0]), "+f"(d[1]), "+f"(d[2]), "+f"(d[3])
        : "r"(a0), "r"(a1), "r"(a2), "r"(a3), "r"(b0), "r"(b1));
}

__device__ __forceinline__ void mma_bf16(float d[4],
    uint32_t a0, uint32_t a1, uint32_t a2, uint32_t a3,
    uint32_t b0, uint32_t b1)
{
    asm volatile(
        "mma.sync.aligned.m16n8k16.row.col.f32.bf16.bf16.f32 "
        "{%0,%1,%2,%3}, {%4,%5,%6,%7}, {%8,%9}, {%0,%1,%2,%3};"
        : "+f"(d[0]), "+f"(d[1]), "+f"(d[2]), "+f"(d[3])
        : "r"(a0), "r"(a1), "r"(a2), "r"(a3), "r"(b0), "r"(b1));
}

__device__ __forceinline__ uint32_t pack_bf16x2(float lo, float hi)
{
    __nv_bfloat162 p = __floats2bfloat162_rn(lo, hi);
    return *reinterpret_cast<uint32_t*>(&p);
}

// ---------------- hi/lo split kernel (RNA tf32 decomposition) ----------------
__global__ __launch_bounds__(256) void split_kernel(
    const float4* __restrict__ src, float4* __restrict__ hi, float4* __restrict__ lo, int n4)
{
    int i = blockIdx.x * 256 + threadIdx.x;
    if (i >= n4) return;
    float4 v = src[i];
    float4 h, l;
    h.x = tf32r(v.x); l.x = tf32r(v.x - h.x);
    h.y = tf32r(v.y); l.y = tf32r(v.y - h.y);
    h.z = tf32r(v.z); l.z = tf32r(v.z - h.z);
    h.w = tf32r(v.w); l.w = tf32r(v.w - h.w);
    hi[i] = h;
    lo[i] = l;
}

// ---------------- 3xTF32 pre-split GEMM + bias: C = A@W + bias ----------------
#define TBM 128
#define TBN 128
#define TBK 16
#define APAD 4
#define BPAD 4
#define AS_STRIDE (TBK + APAD)          // 20
#define BS_STRIDE (TBN + BPAD)          // 132
#define AS_TILE (TBM * AS_STRIDE)       // 2560 floats per buf
#define BS_TILE (TBK * BS_STRIDE)       // 2112 floats per buf
#define OFF_ASH 0
#define OFF_ASL (2 * AS_TILE)
#define OFF_BSH (4 * AS_TILE)
#define OFF_BSL (4 * AS_TILE + 2 * BS_TILE)
#define GEMM_SMEM_BYTES ((4 * AS_TILE + 4 * BS_TILE) * 4)   // 74752

__global__ __launch_bounds__(256) void sgemm_presplit(
    const float* __restrict__ Ahi, const float* __restrict__ Alo,
    const float* __restrict__ Whi, const float* __restrict__ Wlo,
    const float* __restrict__ bias, float* __restrict__ C)
{
    extern __shared__ __align__(16) float sm[];

    const int tid  = threadIdx.x;
    const int lane = tid & 31;
    const int w    = tid >> 5;
    const int gid  = lane >> 2;
    const int tig  = lane & 3;
    const int wm0  = (w >> 2) * 64;   // warp m offset in tile
    const int wn0  = (w & 3) * 32;    // warp n offset in tile
    const int m0   = blockIdx.y * TBM;
    const int n0   = blockIdx.x * TBN;

    float acc[4][4][4];
    #pragma unroll
    for (int mf = 0; mf < 4; mf++)
        #pragma unroll
        for (int nf = 0; nf < 4; nf++)
            #pragma unroll
            for (int r = 0; r < 4; r++) acc[mf][nf][r] = 0.f;

    auto load_tiles = [&](int it, int buf) {
        int k0 = it * TBK;
        #pragma unroll
        for (int j = 0; j < 2; j++) {
            int c = tid + 256 * j;
            int row = c >> 2, seg = c & 3;
            size_t goff = (size_t)(m0 + row) * DQ + k0 + seg * 4;
            int soff = buf * AS_TILE + row * AS_STRIDE + seg * 4;
            uint32_t d0 = (uint32_t)__cvta_generic_to_shared(&sm[OFF_ASH + soff]);
            uint32_t d1 = (uint32_t)__cvta_generic_to_shared(&sm[OFF_ASL + soff]);
            asm volatile("cp.async.ca.shared.global [%0], [%1], 16;" :: "r"(d0), "l"(Ahi + goff));
            asm volatile("cp.async.ca.shared.global [%0], [%1], 16;" :: "r"(d1), "l"(Alo + goff));
        }
        #pragma unroll
        for (int j = 0; j < 2; j++) {
            int c = tid + 256 * j;
            int k = c >> 5, seg = c & 31;
            size_t goff = (size_t)(k0 + k) * DQ + n0 + seg * 4;
            int soff = buf * BS_TILE + k * BS_STRIDE + seg * 4;
            uint32_t d0 = (uint32_t)__cvta_generic_to_shared(&sm[OFF_BSH + soff]);
            uint32_t d1 = (uint32_t)__cvta_generic_to_shared(&sm[OFF_BSL + soff]);
            asm volatile("cp.async.ca.shared.global [%0], [%1], 16;" :: "r"(d0), "l"(Whi + goff));
            asm volatile("cp.async.ca.shared.global [%0], [%1], 16;" :: "r"(d1), "l"(Wlo + goff));
        }
        asm volatile("cp.async.commit_group;");
    };

    load_tiles(0, 0);

    const int NIT = DQ / TBK;   // 64
    for (int it = 0; it < NIT; it++) {
        int buf = it & 1;
        if (it + 1 < NIT) {
            load_tiles(it + 1, buf ^ 1);
            asm volatile("cp.async.wait_group 1;");
        } else {
            asm volatile("cp.async.wait_group 0;");
        }
        __syncthreads();

        #pragma unroll
        for (int ks = 0; ks < 2; ks++) {
            int kk = ks * 8;
            uint32_t ah[4][4], al[4][4];
            #pragma unroll
            for (int mf = 0; mf < 4; mf++) {
                int r = wm0 + mf * 16;
                int i00 = buf * AS_TILE + (r + gid) * AS_STRIDE + kk + tig;
                int i01 = buf * AS_TILE + (r + gid + 8) * AS_STRIDE + kk + tig;
                ah[mf][0] = __float_as_uint(sm[OFF_ASH + i00]);
                ah[mf][1] = __float_as_uint(sm[OFF_ASH + i01]);
                ah[mf][2] = __float_as_uint(sm[OFF_ASH + i00 + 4]);
                ah[mf][3] = __float_as_uint(sm[OFF_ASH + i01 + 4]);
                al[mf][0] = __float_as_uint(sm[OFF_ASL + i00]);
                al[mf][1] = __float_as_uint(sm[OFF_ASL + i01]);
                al[mf][2] = __float_as_uint(sm[OFF_ASL + i00 + 4]);
                al[mf][3] = __float_as_uint(sm[OFF_ASL + i01 + 4]);
            }
            uint32_t bh[4][2], bl[4][2];
            #pragma unroll
            for (int nf = 0; nf < 4; nf++) {
                int cN = wn0 + nf * 8 + gid;
                int i0 = buf * BS_TILE + (kk + tig) * BS_STRIDE + cN;
                int i1 = buf * BS_TILE + (kk + tig + 4) * BS_STRIDE + cN;
                bh[nf][0] = __float_as_uint(sm[OFF_BSH + i0]);
                bh[nf][1] = __float_as_uint(sm[OFF_BSH + i1]);
                bl[nf][0] = __float_as_uint(sm[OFF_BSL + i0]);
                bl[nf][1] = __float_as_uint(sm[OFF_BSL + i1]);
            }
            #pragma unroll
            for (int mf = 0; mf < 4; mf++)
                #pragma unroll
                for (int nf = 0; nf < 4; nf++) {
                    mma_tf32(acc[mf][nf], ah[mf][0], ah[mf][1], ah[mf][2], ah[mf][3],
                             bh[nf][0], bh[nf][1]);
                    mma_tf32(acc[mf][nf], al[mf][0], al[mf][1], al[mf][2], al[mf][3],
                             bh[nf][0], bh[nf][1]);
                    mma_tf32(acc[mf][nf], ah[mf][0], ah[mf][1], ah[mf][2], ah[mf][3],
                             bl[nf][0], bl[nf][1]);
                }
        }
        __syncthreads();
    }

    #pragma unroll
    for (int mf = 0; mf < 4; mf++) {
        #pragma unroll
        for (int nf = 0; nf < 4; nf++) {
            int r0 = m0 + wm0 + mf * 16 + gid;
            int cN = n0 + wn0 + nf * 8 + 2 * tig;
            float2 bv = *(const float2*)(bias + cN);
            float2 o0 = make_float2(acc[mf][nf][0] + bv.x, acc[mf][nf][1] + bv.y);
            float2 o1 = make_float2(acc[mf][nf][2] + bv.x, acc[mf][nf][3] + bv.y);
            *(float2*)(C + (size_t)r0 * DQ + cN) = o0;
            *(float2*)(C + (size_t)(r0 + 8) * DQ + cN) = o1;
        }
    }
}

// ---------------- persistent scan kernel (bf16 mma, fp32 recurrence) ----------
// Per step per CTA: U[64,16] = Cbf[64,1024] @ Wsbf[1024,16] via mma.m16n8k16
// bf16. Warp w owns k-superblocks [4w, 4w+4) (k range 128). k-permutation:
// within superblock s (32 k), lane tig owns global k [32s+8tig, 32s+8tig+8) —
// one LDG.128 of bf16 feeds both mmas of the superblock. Weights pre-laid in
// the matching fragment order. The c recurrence stays fp32; tail writes a bf16
// shadow copy for the next step's mma loads.
// SMEM: Bs 64 mma * 2 nf * 32 lanes * 8B = 32 KB, partials 32 KB
#define SCAN_SMEM_BYTES (32768 + 32768)

__global__ __launch_bounds__(256) void scan_kernel(
    const float* __restrict__ x,  const float* __restrict__ xi,
    const float* __restrict__ xf, const float* __restrict__ xc,
    const float* __restrict__ Wic, const float* __restrict__ Wfc,
    float* __restrict__ cbuf,              // [2][BQ*DQ] fp32
    __nv_bfloat16* __restrict__ cbf,       // [2][BQ*DQ] bf16 shadow
    float* __restrict__ h, int reverse, int epoch)
{
    extern __shared__ __align__(16) char smem_raw[];
    uint2* Bs   = (uint2*)smem_raw;                  // [64 mma][2 nf][32 lanes]
    float* part = (float*)(smem_raw + 32768);        // [8 warps][64 b][16 cols]

    const int tid  = threadIdx.x;
    const int lane = tid & 31;
    const int w    = tid >> 5;
    const int gid  = lane >> 2;       // groupID 0..7
    const int tig  = lane & 3;        // threadID in group
    const int n0   = blockIdx.x * 8;  // this CTA's output column base
    const int bid  = blockIdx.x;

    // ---- pre-lay weights bf16 in fragment order (once per scan) ----
    // mma index mi = 2s+half. b0: k = 32s+8tig+4half+{0,1}; b1: +{2,3}. col = n0+gid.
    for (int idx = tid; idx < 64 * 2 * 32; idx += 256) {
        int l    = idx & 31;
        int nf   = (idx >> 5) & 1;
        int mi   = idx >> 6;
        int s    = mi >> 1;
        int half = mi & 1;
        int k0   = 32 * s + 8 * (l & 3) + 4 * half;
        int col  = n0 + (l >> 2);
        const float* M = nf ? Wfc : Wic;
        uint2 v;
        v.x = pack_bf16x2(M[(size_t)(k0 + 0) * DQ + col], M[(size_t)(k0 + 1) * DQ + col]);
        v.y = pack_bf16x2(M[(size_t)(k0 + 2) * DQ + col], M[(size_t)(k0 + 3) * DQ + col]);
        Bs[idx] = v;
    }
    __syncthreads();

    // tail addressing (constant across steps except t)
    int bbs[2], gns[2];
    #pragma unroll
    for (int rep = 0; rep < 2; rep++) {
        int rr = tid + rep * 256;
        bbs[rep] = rr >> 3;
        gns[rep] = n0 + (rr & 7);
    }

    for (int step = 0; step < LQ; step++) {
        const int t = reverse ? (LQ - 1 - step) : step;
        const float* cprev = cbuf + (step & 1) * (BQ * DQ);
        float* cnext = cbuf + ((step + 1) & 1) * (BQ * DQ);
        const __nv_bfloat16* cbprev = cbf + (step & 1) * (BQ * DQ);
        __nv_bfloat16* cbnext = cbf + ((step + 1) & 1) * (BQ * DQ);

        // ---- prefetch tail operands early ----
        float t_xi[2], t_xf[2], t_xc[2], t_x[2], t_c[2];
        size_t offs[2];
        #pragma unroll
        for (int rep = 0; rep < 2; rep++) {
            size_t off = ((size_t)t * BQ + bbs[rep]) * DQ + gns[rep];
            offs[rep] = off;
            t_xi[rep] = __ldcg(xi + off);
            t_xf[rep] = __ldcg(xf + off);
            t_xc[rep] = __ldcg(xc + off);
            t_x[rep]  = __ldcg(x + off);
            t_c[rep]  = __ldcg(cprev + (size_t)bbs[rep] * DQ + gns[rep]);
        }

        float acc[4][2][4];
        #pragma unroll
        for (int m = 0; m < 4; m++)
            #pragma unroll
            for (int nf = 0; nf < 2; nf++)
                #pragma unroll
                for (int r = 0; r < 4; r++) acc[m][nf][r] = 0.f;

        #pragma unroll
        for (int j = 0; j < 4; j++) {
            int s = 4 * w + j;
            uint2 bu0 = Bs[((2 * s + 0) * 2 + 0) * 32 + lane];
            uint2 bv0 = Bs[((2 * s + 0) * 2 + 1) * 32 + lane];
            uint2 bu1 = Bs[((2 * s + 1) * 2 + 0) * 32 + lane];
            uint2 bv1 = Bs[((2 * s + 1) * 2 + 1) * 32 + lane];
            const __nv_bfloat16* abase = cbprev + (size_t)gid * DQ + 32 * s + 8 * tig;
            uint4 av[8];
            #pragma unroll
            for (int m = 0; m < 4; m++) {
                av[2 * m]     = __ldcg((const uint4*)(abase + (size_t)(m * 16) * DQ));
                av[2 * m + 1] = __ldcg((const uint4*)(abase + (size_t)(m * 16 + 8) * DQ));
            }
            #pragma unroll
            for (int m = 0; m < 4; m++) {
                // mma half 0: k = 32s+8tig+{0..3}
                mma_bf16(acc[m][0], av[2*m].x, av[2*m+1].x, av[2*m].y, av[2*m+1].y,
                         bu0.x, bu0.y);
                mma_bf16(acc[m][1], av[2*m].x, av[2*m+1].x, av[2*m].y, av[2*m+1].y,
                         bv0.x, bv0.y);
                // mma half 1: k = 32s+8tig+{4..7}
                mma_bf16(acc[m][0], av[2*m].z, av[2*m+1].z, av[2*m].w, av[2*m+1].w,
                         bu1.x, bu1.y);
                mma_bf16(acc[m][1], av[2*m].z, av[2*m+1].z, av[2*m].w, av[2*m+1].w,
                         bv1.x, bv1.y);
            }
        }

        // ---- write split-K partials: part[w][b][col] ----
        #pragma unroll
        for (int m = 0; m < 4; m++) {
            #pragma unroll
            for (int nf = 0; nf < 2; nf++) {
                int col = nf * 8 + 2 * tig;
                int b0r = m * 16 + gid;
                float2* p0 = (float2*)&part[((w * 64) + b0r) * 16 + col];
                float2* p1 = (float2*)&part[((w * 64) + b0r + 8) * 16 + col];
                *p0 = make_float2(acc[m][nf][0], acc[m][nf][1]);
                *p1 = make_float2(acc[m][nf][2], acc[m][nf][3]);
            }
        }
        __syncthreads();

        // ---- reduce over warps + elementwise update: 64b x 8n, 2 per thread ----
        #pragma unroll
        for (int rep = 0; rep < 2; rep++) {
            int rr = tid + rep * 256;
            int bb = rr >> 3, nn = rr & 7;
            float uu = 0.f, vv = 0.f;
            #pragma unroll
            for (int ww = 0; ww < 8; ww++) {
                uu += part[((ww * 64) + bb) * 16 + nn];
                vv += part[((ww * 64) + bb) * 16 + 8 + nn];
            }
            float iv = 1.0f / (1.0f + expf(-(t_xi[rep] + uu)));
            float fv = 1.0f / (1.0f + expf(-(t_xf[rep] + vv)));
            float cn = iv * t_xc[rep] + fv * t_c[rep];
            size_t coff = (size_t)bb * DQ + gns[rep];
            cnext[coff] = cn;
            cbnext[coff] = __float2bfloat16_rn(cn);
            h[offs[rep]] = tanhf(cn) + t_x[rep];
        }

        // ---- distributed flag barrier (parallel arrivals, no atomic chain) ----
        {
            const unsigned val = (unsigned)(epoch + step + 1);
            __syncthreads();
            if (tid == 0)
                asm volatile("st.release.gpu.global.u32 [%0], %1;"
                             :: "l"(g_flags + bid), "r"(val) : "memory");
            if (bid == 0) {
                if (tid < NB_SCAN) {
                    unsigned v;
                    do {
                        asm volatile("ld.acquire.gpu.global.u32 %0, [%1];"
                                     : "=r"(v) : "l"(g_flags + tid) : "memory");
                    } while (v < val);
                }
                __syncthreads();
                if (tid == 0)
                    asm volatile("st.release.gpu.global.u32 [%0], %1;"
                                 :: "l"(g_flags + NB_SCAN), "r"(val) : "memory");
            } else {
                if (tid == 0) {
                    unsigned v;
                    do {
                        asm volatile("ld.acquire.gpu.global.u32 %0, [%1];"
                                     : "=r"(v) : "l"(g_flags + NB_SCAN) : "memory");
                    } while (v < val);
                }
            }
            __syncthreads();
        }
    }
}

// ---------------- launcher ----------------
extern "C" void kernel_launch(void* const* d_in, const int* in_sizes, int n_in,
                              void* d_out, int out_size)
{
    (void)in_sizes; (void)n_in; (void)out_size;

    cudaFuncSetAttribute(scan_kernel, cudaFuncAttributeMaxDynamicSharedMemorySize,
                         SCAN_SMEM_BYTES);
    cudaFuncSetAttribute(sgemm_presplit, cudaFuncAttributeMaxDynamicSharedMemorySize,
                         GEMM_SMEM_BYTES);

    const int*   xs  = (const int*)d_in[0];
    const float* emb = (const float*)d_in[1];
    const float* P[16];
    for (int i = 0; i < 16; i++) P[i] = (const float*)d_in[2 + i];
    // P: 0=fw_Wix 1=fw_Wic 2=fw_Wfx 3=fw_Wfc 4=fw_Wcx 5=fw_bi 6=fw_bf 7=fw_bc
    //    8=bw_Wix 9=bw_Wic 10=bw_Wfx 11=bw_Wfc 12=bw_Wcx 13=bw_bi 14=bw_bf 15=bw_bc

    float *px, *ph, *pxi, *pxf, *pxc, *pcb, *pahi, *palo, *pwhi, *pwlo;
    __nv_bfloat16* pcbf;
    unsigned* pflags;
    cudaGetSymbolAddress((void**)&px,    g_x);
    cudaGetSymbolAddress((void**)&ph,    g_h);
    cudaGetSymbolAddress((void**)&pxi,   g_xi);
    cudaGetSymbolAddress((void**)&pxf,   g_xf);
    cudaGetSymbolAddress((void**)&pxc,   g_xc);
    cudaGetSymbolAddress((void**)&pcb,   g_cbuf);
    cudaGetSymbolAddress((void**)&pcbf,  g_cbf);
    cudaGetSymbolAddress((void**)&pahi,  g_ahi);
    cudaGetSymbolAddress((void**)&palo,  g_alo);
    cudaGetSymbolAddress((void**)&pwhi,  g_whi);
    cudaGetSymbolAddress((void**)&pwlo,  g_wlo);
    cudaGetSymbolAddress((void**)&pflags, g_flags);
    float* out = (float*)d_out;

    embed_kernel<<<MQ * DQ / 4 / 256, 256>>>(xs, emb, px);
    zero_kernel<<<(2 * BQ * DQ + 255) / 256, 256>>>(pcb, 2 * BQ * DQ);
    zero_kernel<<<(BQ * DQ + 255) / 256, 256>>>((float*)pcbf, BQ * DQ); // 2*BQ*DQ bf16
    zero_kernel<<<1, 256>>>((float*)pflags, NB_SCAN + 1);

    // pre-split the 6 input-projection weight matrices (once per launch)
    const int WN4 = DQ * DQ / 4;                // 262144
    const int widx[6] = {0, 2, 4, 8, 10, 12};   // Wix, Wfx, Wcx for fw then bw
    for (int j = 0; j < 6; j++) {
        split_kernel<<<WN4 / 256, 256>>>((const float4*)P[widx[j]],
                                         (float4*)(pwhi + (size_t)j * DQ * DQ),
                                         (float4*)(pwlo + (size_t)j * DQ * DQ), WN4);
    }

    const int AN4 = MQ * DQ / 4;                // 4M
    dim3 ggrid(DQ / TBN, MQ / TBM);             // (8, 128)
    for (int layer = 0; layer < 2; layer++) {
        // forward direction
        split_kernel<<<AN4 / 256, 256>>>((const float4*)px, (float4*)pahi, (float4*)palo, AN4);
        sgemm_presplit<<<ggrid, 256, GEMM_SMEM_BYTES>>>(pahi, palo,
            pwhi + 0 * (size_t)DQ * DQ, pwlo + 0 * (size_t)DQ * DQ, P[5], pxi);
        sgemm_presplit<<<ggrid, 256, GEMM_SMEM_BYTES>>>(pahi, palo,
            pwhi + 1 * (size_t)DQ * DQ, pwlo + 1 * (size_t)DQ * DQ, P[6], pxf);
        sgemm_presplit<<<ggrid, 256, GEMM_SMEM_BYTES>>>(pahi, palo,
            pwhi + 2 * (size_t)DQ * DQ, pwlo + 2 * (size_t)DQ * DQ, P[7], pxc);
        scan_kernel<<<NB_SCAN, 256, SCAN_SMEM_BYTES>>>(px, pxi, pxf, pxc,
            P[1], P[3], pcb, pcbf, ph, 0, (layer * 2 + 0) * LQ);
        // backward direction
        split_kernel<<<AN4 / 256, 256>>>((const float4*)ph, (float4*)pahi, (float4*)palo, AN4);
        sgemm_presplit<<<ggrid, 256, GEMM_SMEM_BYTES>>>(pahi, palo,
            pwhi + 3 * (size_t)DQ * DQ, pwlo + 3 * (size_t)DQ * DQ, P[13], pxi);
        sgemm_presplit<<<ggrid, 256, GEMM_SMEM_BYTES>>>(pahi, palo,
            pwhi + 4 * (size_t)DQ * DQ, pwlo + 4 * (size_t)DQ * DQ, P[14], pxf);
        sgemm_presplit<<<ggrid, 256, GEMM_SMEM_BYTES>>>(pahi, palo,
            pwhi + 5 * (size_t)DQ * DQ, pwlo + 5 * (size_t)DQ * DQ, P[15], pxc);
        float* ho = (layer == 1) ? out : px;
        scan_kernel<<<NB_SCAN, 256, SCAN_SMEM_BYTES>>>(ph, pxi, pxf, pxc,
            P[9], P[11], pcb, pcbf, ho, 1, (layer * 2 + 1) * LQ);
    }
}